// round 5
// baseline (speedup 1.0000x reference)
#include <cuda_runtime.h>

// Problem constants
#define BATCH   4096
#define IND     40          // STATE_DIM + ACTION_DIM
#define HID     128
#define DIMS    33
#define ENS     10
#define DE      (DIMS * ENS)   // 330
#define BT      128            // batch rows per tile
#define BSPLIT  4              // batch split across CTAs
#define ROWS_PER_CTA (BATCH / BSPLIT)   // 1024
#define NTHREADS 256

// Shared memory layout (floats)
#define XS_OFF   0                               // [IND][BT]      x tile, K-major
#define W1S_OFF  (XS_OFF  + IND * BT)            // [IND][HID]     W1^T, K-major
#define W2S_OFF  (W1S_OFF + IND * HID)           // [HID][HID+1]   W2^T, K-major, padded
#define H1S_OFF  (W2S_OFF + HID * (HID + 1))     // [HID][BT+1]    h1, K-major, padded
#define B1S_OFF  (H1S_OFF + HID * (BT + 1))
#define B2S_OFF  (B1S_OFF + HID)
#define W3S_OFF  (B2S_OFF + HID)                 // [2][HID]
#define B3S_OFF  (W3S_OFF + 2 * HID)
#define SMEM_FLOATS (B3S_OFF + 2)
#define SMEM_BYTES  (SMEM_FLOATS * 4)            // 175112 B

__device__ __forceinline__ float silu_f(float v) {
    // v * sigmoid(v) = v / (1 + e^-v)
    return __fdividef(v, 1.0f + __expf(-v));
}

__device__ __forceinline__ float softplus_f(float v) {
    // log1p(exp(v)), overflow-safe
    return (v > 20.0f) ? v : log1pf(__expf(v));
}

__global__ __launch_bounds__(NTHREADS, 1)
void ens_mlp_kernel(const float* __restrict__ x,
                    const float* __restrict__ W1, const float* __restrict__ b1,
                    const float* __restrict__ W2, const float* __restrict__ b2,
                    const float* __restrict__ W3, const float* __restrict__ b3,
                    float* __restrict__ out)
{
    extern __shared__ float sm[];
    const int tid = threadIdx.x;
    const int tx  = tid & 15;      // n-dim group (column)
    const int ty  = tid >> 4;      // m-dim group (row)
    const int de  = blockIdx.x;    // d*ENS + e  (matches [D,E,...] flatten)
    const int row_base = blockIdx.y * ROWS_PER_CTA;

    // ---- Load per-(d,e) weights into SMEM (K-major, padded), vectorized ----
    {
        // W1: [HID][IND] global -> W1s[i][n] (transpose). IND=40 = 10 float4.
        const float4* gW1 = (const float4*)(W1 + (size_t)de * HID * IND);
        for (int idx = tid; idx < HID * (IND / 4); idx += NTHREADS) {
            int n = idx / (IND / 4), i4 = idx - n * (IND / 4);
            float4 v = gW1[idx];
            int i = i4 * 4;
            sm[W1S_OFF + (i + 0) * HID + n] = v.x;
            sm[W1S_OFF + (i + 1) * HID + n] = v.y;
            sm[W1S_OFF + (i + 2) * HID + n] = v.z;
            sm[W1S_OFF + (i + 3) * HID + n] = v.w;
        }
        // W2: [HID][HID] global -> W2s[h][g] (transpose), padded rows.
        const float4* gW2 = (const float4*)(W2 + (size_t)de * HID * HID);
        for (int idx = tid; idx < HID * (HID / 4); idx += NTHREADS) {
            int g = idx >> 5, h4 = idx & 31;
            float4 v = gW2[idx];
            int h = h4 * 4;
            sm[W2S_OFF + (h + 0) * (HID + 1) + g] = v.x;
            sm[W2S_OFF + (h + 1) * (HID + 1) + g] = v.y;
            sm[W2S_OFF + (h + 2) * (HID + 1) + g] = v.z;
            sm[W2S_OFF + (h + 3) * (HID + 1) + g] = v.w;
        }
        // W3: [2][HID] direct copy.
        const float4* gW3 = (const float4*)(W3 + (size_t)de * 2 * HID);
        for (int idx = tid; idx < 2 * HID / 4; idx += NTHREADS)
            ((float4*)(sm + W3S_OFF))[idx] = gW3[idx];
        for (int idx = tid; idx < HID; idx += NTHREADS) {
            sm[B1S_OFF + idx] = b1[(size_t)de * HID + idx];
            sm[B2S_OFF + idx] = b2[(size_t)de * HID + idx];
        }
        if (tid < 2) sm[B3S_OFF + tid] = b3[de * 2 + tid];
    }
    // (visibility of the weight stores is covered by the first tile's __syncthreads)

    const int ntiles = ROWS_PER_CTA / BT;
    for (int t = 0; t < ntiles; ++t) {
        const int row0 = row_base + t * BT;

        // ---- Load X tile, K-major (Xs[k][m]); row = 10 float4 ----
        {
            const float4* gx = (const float4*)(x + (size_t)row0 * IND);
            for (int idx = tid; idx < BT * (IND / 4); idx += NTHREADS) {
                int r = idx / (IND / 4), c4 = idx - r * (IND / 4);
                float4 v = gx[idx];
                int c = c4 * 4;
                sm[XS_OFF + (c + 0) * BT + r] = v.x;
                sm[XS_OFF + (c + 1) * BT + r] = v.y;
                sm[XS_OFF + (c + 2) * BT + r] = v.z;
                sm[XS_OFF + (c + 3) * BT + r] = v.w;
            }
        }
        __syncthreads();

        // ---- Layer 1: h1 = silu(X @ W1^T + b1), M=128 N=128 K=40 ----
        float acc[8][8];
        #pragma unroll
        for (int j = 0; j < 8; ++j) {
            float bj = sm[B1S_OFF + tx + 16 * j];
            #pragma unroll
            for (int i = 0; i < 8; ++i) acc[i][j] = bj;
        }
        #pragma unroll 4
        for (int k = 0; k < IND; ++k) {
            float a[8], bb[8];
            #pragma unroll
            for (int i = 0; i < 8; ++i) a[i] = sm[XS_OFF + k * BT + ty + 16 * i];
            #pragma unroll
            for (int j = 0; j < 8; ++j) bb[j] = sm[W1S_OFF + k * HID + tx + 16 * j];
            #pragma unroll
            for (int i = 0; i < 8; ++i)
                #pragma unroll
                for (int j = 0; j < 8; ++j)
                    acc[i][j] = fmaf(a[i], bb[j], acc[i][j]);
        }
        // SiLU + store h1 K-major: H1s[n][m]
        #pragma unroll
        for (int j = 0; j < 8; ++j) {
            int n = tx + 16 * j;
            #pragma unroll
            for (int i = 0; i < 8; ++i) {
                int m = ty + 16 * i;
                sm[H1S_OFF + n * (BT + 1) + m] = silu_f(acc[i][j]);
            }
        }
        __syncthreads();

        // ---- Layer 2: h2 = silu(h1 @ W2^T + b2), M=128 N=128 K=128 ----
        #pragma unroll
        for (int j = 0; j < 8; ++j) {
            float bj = sm[B2S_OFF + tx + 16 * j];
            #pragma unroll
            for (int i = 0; i < 8; ++i) acc[i][j] = bj;
        }
        #pragma unroll 4
        for (int k = 0; k < HID; ++k) {
            float a[8], bb[8];
            #pragma unroll
            for (int i = 0; i < 8; ++i) a[i] = sm[H1S_OFF + k * (BT + 1) + ty + 16 * i];
            #pragma unroll
            for (int j = 0; j < 8; ++j) bb[j] = sm[W2S_OFF + k * (HID + 1) + tx + 16 * j];
            #pragma unroll
            for (int i = 0; i < 8; ++i)
                #pragma unroll
                for (int j = 0; j < 8; ++j)
                    acc[i][j] = fmaf(a[i], bb[j], acc[i][j]);
        }

        // ---- Layer 3 + epilogue: out = silu(h2) @ W3^T + b3 ----
        const float b3_0 = sm[B3S_OFF + 0];
        const float b3_1 = sm[B3S_OFF + 1];
        #pragma unroll
        for (int i = 0; i < 8; ++i) {
            float s0 = 0.0f, s1 = 0.0f;
            #pragma unroll
            for (int j = 0; j < 8; ++j) {
                float v = silu_f(acc[i][j]);
                int n = tx + 16 * j;
                s0 = fmaf(v, sm[W3S_OFF + n],       s0);
                s1 = fmaf(v, sm[W3S_OFF + HID + n], s1);
            }
            // reduce over tx (16 lanes within each half-warp)
            #pragma unroll
            for (int off = 8; off >= 1; off >>= 1) {
                s0 += __shfl_xor_sync(0xffffffffu, s0, off);
                s1 += __shfl_xor_sync(0xffffffffu, s1, off);
            }
            if (tx == 0) {
                int b = row0 + ty + 16 * i;
                float mean = s0 + b3_0;
                float lv   = s1 + b3_1;
                // soft clamp: MAX - softplus(MAX - lv); MIN + softplus(lv - MIN)
                lv = 5.0f  - softplus_f(5.0f - lv);
                lv = -10.0f + softplus_f(lv + 10.0f);
                out[(size_t)b * DE + de]                       = mean;
                out[(size_t)BATCH * DE + (size_t)b * DE + de]  = lv;
            }
        }
        __syncthreads();  // before next tile overwrites Xs / H1s
    }
}

extern "C" void kernel_launch(void* const* d_in, const int* in_sizes, int n_in,
                              void* d_out, int out_size)
{
    const float* x  = (const float*)d_in[0];
    const float* W1 = (const float*)d_in[1];
    const float* b1 = (const float*)d_in[2];
    const float* W2 = (const float*)d_in[3];
    const float* b2 = (const float*)d_in[4];
    const float* W3 = (const float*)d_in[5];
    const float* b3 = (const float*)d_in[6];
    float* out = (float*)d_out;

    cudaFuncSetAttribute(ens_mlp_kernel,
                         cudaFuncAttributeMaxDynamicSharedMemorySize, SMEM_BYTES);

    dim3 grid(DE, BSPLIT);
    ens_mlp_kernel<<<grid, NTHREADS, SMEM_BYTES>>>(x, W1, b1, W2, b2, W3, b3, out);
}

// round 7
// speedup vs baseline: 1.1020x; 1.1020x over previous
#include <cuda_runtime.h>

// Problem constants
#define BATCH   4096
#define IND     40          // STATE_DIM + ACTION_DIM
#define HID     128
#define DIMS    33
#define ENS     10
#define DE      (DIMS * ENS)   // 330
#define BT      128            // batch rows per tile
#define BSPLIT  4              // batch split across CTAs
#define ROWS_PER_CTA (BATCH / BSPLIT)   // 1024
#define NTHREADS 256

#define W2STRIDE (HID + 2)     // 130: keeps 8B alignment for LDS.64 pair reads

// Shared memory layout (floats) — all pair-read regions 8B aligned
#define XS_OFF   0                               // [IND][BT]        x tile, K-major
#define W1S_OFF  (XS_OFF  + IND * BT)            // [IND][HID]       W1^T, K-major
#define W2S_OFF  (W1S_OFF + IND * HID)           // [HID][W2STRIDE]  W2^T, K-major
#define H1S_OFF  (W2S_OFF + HID * W2STRIDE)      // [HID][BT+1]      h1, K-major
#define B1S_OFF  (H1S_OFF + HID * (BT + 1))
#define B2S_OFF  (B1S_OFF + HID)
#define W3S_OFF  (B2S_OFF + HID)                 // [2][HID]
#define B3S_OFF  (W3S_OFF + 2 * HID)
#define SMEM_FLOATS (B3S_OFF + 2)
#define SMEM_BYTES  (SMEM_FLOATS * 4)            // ~175.6 KB

__device__ __forceinline__ float silu_f(float v) {
    return __fdividef(v, 1.0f + __expf(-v));
}

__device__ __forceinline__ float softplus_f(float v) {
    return (v > 20.0f) ? v : log1pf(__expf(v));
}

// ---- packed fp32x2 helpers (Blackwell FFMA2 path) ----
__device__ __forceinline__ unsigned long long pack2_dup(float v) {
    unsigned long long r;
    asm("mov.b64 %0, {%1, %1};" : "=l"(r) : "f"(v));
    return r;
}
__device__ __forceinline__ void unpack2(unsigned long long v, float& lo, float& hi) {
    asm("mov.b64 {%0, %1}, %2;" : "=f"(lo), "=f"(hi) : "l"(v));
}
__device__ __forceinline__ unsigned long long ffma2(unsigned long long a,
                                                    unsigned long long b,
                                                    unsigned long long c) {
    unsigned long long d;
    asm("fma.rn.f32x2 %0, %1, %2, %3;" : "=l"(d) : "l"(a), "l"(b), "l"(c));
    return d;
}

__global__ __launch_bounds__(NTHREADS, 1)
void ens_mlp_kernel(const float* __restrict__ x,
                    const float* __restrict__ W1, const float* __restrict__ b1,
                    const float* __restrict__ W2, const float* __restrict__ b2,
                    const float* __restrict__ W3, const float* __restrict__ b3,
                    float* __restrict__ out)
{
    extern __shared__ float sm[];
    const int tid = threadIdx.x;
    const int tx  = tid & 15;      // column-pair group: n = 2*tx + 32*j + o
    const int ty  = tid >> 4;      // row group: m = ty + 16*i
    const int de  = blockIdx.x;
    const int row_base = blockIdx.y * ROWS_PER_CTA;

    // ---- Load per-(d,e) weights into SMEM (K-major), vectorized ----
    {
        const float4* gW1 = (const float4*)(W1 + (size_t)de * HID * IND);
        for (int idx = tid; idx < HID * (IND / 4); idx += NTHREADS) {
            int n = idx / (IND / 4), i4 = idx - n * (IND / 4);
            float4 v = gW1[idx];
            int i = i4 * 4;
            sm[W1S_OFF + (i + 0) * HID + n] = v.x;
            sm[W1S_OFF + (i + 1) * HID + n] = v.y;
            sm[W1S_OFF + (i + 2) * HID + n] = v.z;
            sm[W1S_OFF + (i + 3) * HID + n] = v.w;
        }
        const float4* gW2 = (const float4*)(W2 + (size_t)de * HID * HID);
        for (int idx = tid; idx < HID * (HID / 4); idx += NTHREADS) {
            int g = idx >> 5, h4 = idx & 31;
            float4 v = gW2[idx];
            int h = h4 * 4;
            sm[W2S_OFF + (h + 0) * W2STRIDE + g] = v.x;
            sm[W2S_OFF + (h + 1) * W2STRIDE + g] = v.y;
            sm[W2S_OFF + (h + 2) * W2STRIDE + g] = v.z;
            sm[W2S_OFF + (h + 3) * W2STRIDE + g] = v.w;
        }
        const float4* gW3 = (const float4*)(W3 + (size_t)de * 2 * HID);
        for (int idx = tid; idx < 2 * HID / 4; idx += NTHREADS)
            ((float4*)(sm + W3S_OFF))[idx] = gW3[idx];
        for (int idx = tid; idx < HID; idx += NTHREADS) {
            sm[B1S_OFF + idx] = b1[(size_t)de * HID + idx];
            sm[B2S_OFF + idx] = b2[(size_t)de * HID + idx];
        }
        if (tid < 2) sm[B3S_OFF + tid] = b3[de * 2 + tid];
    }

    const int col0 = 2 * tx;   // base column of this thread's pairs

    const int ntiles = ROWS_PER_CTA / BT;
    for (int t = 0; t < ntiles; ++t) {
        const int row0 = row_base + t * BT;

        // ---- Load X tile, K-major (Xs[k][m]) ----
        {
            const float4* gx = (const float4*)(x + (size_t)row0 * IND);
            for (int idx = tid; idx < BT * (IND / 4); idx += NTHREADS) {
                int r = idx / (IND / 4), c4 = idx - r * (IND / 4);
                float4 v = gx[idx];
                int c = c4 * 4;
                sm[XS_OFF + (c + 0) * BT + r] = v.x;
                sm[XS_OFF + (c + 1) * BT + r] = v.y;
                sm[XS_OFF + (c + 2) * BT + r] = v.z;
                sm[XS_OFF + (c + 3) * BT + r] = v.w;
            }
        }
        __syncthreads();

        // ---- Layer 1: h1 = silu(X @ W1^T + b1), packed fp32x2 ----
        unsigned long long acc2[8][4];
        #pragma unroll
        for (int j = 0; j < 4; ++j) {
            unsigned long long bj =
                *(const unsigned long long*)(sm + B1S_OFF + col0 + 32 * j);
            #pragma unroll
            for (int i = 0; i < 8; ++i) acc2[i][j] = bj;
        }
        #pragma unroll 4
        for (int k = 0; k < IND; ++k) {
            unsigned long long ap[8], bp[4];
            #pragma unroll
            for (int i = 0; i < 8; ++i)
                ap[i] = pack2_dup(sm[XS_OFF + k * BT + ty + 16 * i]);
            #pragma unroll
            for (int j = 0; j < 4; ++j)
                bp[j] = *(const unsigned long long*)
                        (sm + W1S_OFF + k * HID + col0 + 32 * j);
            #pragma unroll
            for (int i = 0; i < 8; ++i)
                #pragma unroll
                for (int j = 0; j < 4; ++j)
                    acc2[i][j] = ffma2(ap[i], bp[j], acc2[i][j]);
        }
        // SiLU + store h1 K-major: H1s[n][m]
        #pragma unroll
        for (int j = 0; j < 4; ++j) {
            int n0 = col0 + 32 * j;
            #pragma unroll
            for (int i = 0; i < 8; ++i) {
                int m = ty + 16 * i;
                float v0, v1;
                unpack2(acc2[i][j], v0, v1);
                sm[H1S_OFF + (n0 + 0) * (BT + 1) + m] = silu_f(v0);
                sm[H1S_OFF + (n0 + 1) * (BT + 1) + m] = silu_f(v1);
            }
        }
        __syncthreads();

        // ---- Layer 2: h2 = silu(h1 @ W2^T + b2), packed fp32x2 ----
        #pragma unroll
        for (int j = 0; j < 4; ++j) {
            unsigned long long bj =
                *(const unsigned long long*)(sm + B2S_OFF + col0 + 32 * j);
            #pragma unroll
            for (int i = 0; i < 8; ++i) acc2[i][j] = bj;
        }
        #pragma unroll 4
        for (int k = 0; k < HID; ++k) {
            unsigned long long ap[8], bp[4];
            #pragma unroll
            for (int i = 0; i < 8; ++i)
                ap[i] = pack2_dup(sm[H1S_OFF + k * (BT + 1) + ty + 16 * i]);
            #pragma unroll
            for (int j = 0; j < 4; ++j)
                bp[j] = *(const unsigned long long*)
                        (sm + W2S_OFF + k * W2STRIDE + col0 + 32 * j);
            #pragma unroll
            for (int i = 0; i < 8; ++i)
                #pragma unroll
                for (int j = 0; j < 4; ++j)
                    acc2[i][j] = ffma2(ap[i], bp[j], acc2[i][j]);
        }

        // ---- Layer 3 + epilogue ----
        const float b3_0 = sm[B3S_OFF + 0];
        const float b3_1 = sm[B3S_OFF + 1];
        #pragma unroll
        for (int i = 0; i < 8; ++i) {
            float s0 = 0.0f, s1 = 0.0f;
            #pragma unroll
            for (int j = 0; j < 4; ++j) {
                int n0 = col0 + 32 * j;
                float v0, v1;
                unpack2(acc2[i][j], v0, v1);
                v0 = silu_f(v0);
                v1 = silu_f(v1);
                s0 = fmaf(v0, sm[W3S_OFF + n0],           s0);
                s0 = fmaf(v1, sm[W3S_OFF + n0 + 1],       s0);
                s1 = fmaf(v0, sm[W3S_OFF + HID + n0],     s1);
                s1 = fmaf(v1, sm[W3S_OFF + HID + n0 + 1], s1);
            }
            #pragma unroll
            for (int off = 8; off >= 1; off >>= 1) {
                s0 += __shfl_xor_sync(0xffffffffu, s0, off);
                s1 += __shfl_xor_sync(0xffffffffu, s1, off);
            }
            if (tx == 0) {
                int b = row0 + ty + 16 * i;
                float mean = s0 + b3_0;
                float lv   = s1 + b3_1;
                lv = 5.0f   - softplus_f(5.0f - lv);
                lv = -10.0f + softplus_f(lv + 10.0f);
                out[(size_t)b * DE + de]                      = mean;
                out[(size_t)BATCH * DE + (size_t)b * DE + de] = lv;
            }
        }
        __syncthreads();  // before next tile overwrites Xs / H1s
    }
}

extern "C" void kernel_launch(void* const* d_in, const int* in_sizes, int n_in,
                              void* d_out, int out_size)
{
    const float* x  = (const float*)d_in[0];
    const float* W1 = (const float*)d_in[1];
    const float* b1 = (const float*)d_in[2];
    const float* W2 = (const float*)d_in[3];
    const float* b2 = (const float*)d_in[4];
    const float* W3 = (const float*)d_in[5];
    const float* b3 = (const float*)d_in[6];
    float* out = (float*)d_out;

    cudaFuncSetAttribute(ens_mlp_kernel,
                         cudaFuncAttributeMaxDynamicSharedMemorySize, SMEM_BYTES);

    dim3 grid(DE, BSPLIT);
    ens_mlp_kernel<<<grid, NTHREADS, SMEM_BYTES>>>(x, W1, b1, W2, b2, W3, b3, out);
}

// round 12
// speedup vs baseline: 2.3232x; 2.1081x over previous
#include <cuda_runtime.h>
#include <cuda_bf16.h>
#include <cstdint>

// ---------------- Problem constants ----------------
#define BATCH   4096
#define IND     40
#define HID     128
#define DE      330
#define BT      128
#define BSPLIT  4
#define ROWS_PER_CTA 1024
#define NT      256

// ---------------- SMEM byte layout ----------------
#define A_HI    0                   // [128][136 bf16] pitch 272B; x / h1 hi; also h2 fp32 (pitch 129 f)
#define A_LO    34816               // [128][136 bf16]
#define B2_HI   69632               // [128][136 bf16] W2 hi
#define B2_LO   104448
#define B1_HI   139264              // [128][56 bf16] pitch 112B, K padded 40->48
#define B1_LO   153600
#define SCAL    167936              // float region
#define APITCH  272                 // bytes
#define B1PITCH 112                 // bytes
#define H2PITCH 129                 // floats
// scalar float indices (relative to SCAL)
#define W3F 0                       // [2][128]
#define B1F 256
#define B2F 384
#define B3F 512
#define PSF 516                     // [2 halves][128 rows][2]
#define SMEM_BYTES (SCAL + (PSF + 512) * 4)   // 172048 B

// ---------------- helpers ----------------
__device__ __forceinline__ float silu_f(float v) {
    return __fdividef(v, 1.0f + __expf(-v));
}
__device__ __forceinline__ float softplus_f(float v) {
    return (v > 20.0f) ? v : log1pf(__expf(v));
}
__device__ __forceinline__ float bf16_of(float v) {
    return __bfloat162float(__float2bfloat16_rn(v));
}
__device__ __forceinline__ uint32_t pack_bf2(float a, float b) {
    uint32_t lo = __bfloat16_as_ushort(__float2bfloat16_rn(a));
    uint32_t hi = __bfloat16_as_ushort(__float2bfloat16_rn(b));
    return lo | (hi << 16);
}
__device__ __forceinline__ uint32_t lds_u32(const char* p) {
    return *(const uint32_t*)p;
}

// mma.sync m16n8k16 bf16, fp32 accumulate (baseline PTX, no arch-specific features)
__device__ __forceinline__ void mma_bf16(float (&d)[4],
                                         uint32_t a0, uint32_t a1, uint32_t a2, uint32_t a3,
                                         uint32_t b0, uint32_t b1) {
    asm volatile(
        "mma.sync.aligned.m16n8k16.row.col.f32.bf16.bf16.f32 "
        "{%0,%1,%2,%3}, {%4,%5,%6,%7}, {%8,%9}, {%0,%1,%2,%3};"
        : "+f"(d[0]), "+f"(d[1]), "+f"(d[2]), "+f"(d[3])
        : "r"(a0), "r"(a1), "r"(a2), "r"(a3), "r"(b0), "r"(b1));
}

__global__ __launch_bounds__(NT, 1)
void ens_mlp_mma_kernel(const float* __restrict__ x,
                        const float* __restrict__ W1, const float* __restrict__ b1,
                        const float* __restrict__ W2, const float* __restrict__ b2,
                        const float* __restrict__ W3, const float* __restrict__ b3,
                        float* __restrict__ out)
{
    extern __shared__ char smc[];
    float* smf = (float*)(smc + SCAL);
    const int tid  = threadIdx.x;
    const int wid  = tid >> 5;
    const int lane = tid & 31;
    const int g = lane >> 2, t = lane & 3;
    const int warp_m = wid & 3;        // 4 m-groups of 32 rows
    const int warp_n = wid >> 2;       // 2 n-groups of 64 cols
    const int de = blockIdx.x;
    const int row_base = blockIdx.y * ROWS_PER_CTA;

    // ---- Weight prep: bf16 hi/lo splits into SMEM (once per CTA) ----
    {
        const float* gW1 = W1 + (size_t)de * HID * IND;
        for (int idx = tid; idx < HID * 48; idx += NT) {
            int n = idx / 48, k = idx - n * 48;
            float v = (k < IND) ? gW1[n * IND + k] : 0.0f;
            float vh = bf16_of(v);
            *(__nv_bfloat16*)(smc + B1_HI + n * B1PITCH + 2 * k) = __float2bfloat16_rn(v);
            *(__nv_bfloat16*)(smc + B1_LO + n * B1PITCH + 2 * k) = __float2bfloat16_rn(v - vh);
        }
        const float* gW2 = W2 + (size_t)de * HID * HID;
        for (int idx = tid; idx < HID * HID; idx += NT) {
            int n = idx >> 7, k = idx & 127;
            float v = gW2[idx];
            float vh = bf16_of(v);
            *(__nv_bfloat16*)(smc + B2_HI + n * APITCH + 2 * k) = __float2bfloat16_rn(v);
            *(__nv_bfloat16*)(smc + B2_LO + n * APITCH + 2 * k) = __float2bfloat16_rn(v - vh);
        }
        const float* gW3 = W3 + (size_t)de * 2 * HID;
        for (int idx = tid; idx < 256; idx += NT) smf[W3F + idx] = gW3[idx];
        for (int idx = tid; idx < HID; idx += NT) {
            smf[B1F + idx] = b1[(size_t)de * HID + idx];
            smf[B2F + idx] = b2[(size_t)de * HID + idx];
        }
        if (tid < 2) smf[B3F + tid] = b3[de * 2 + tid];
    }

    for (int tIdx = 0; tIdx < ROWS_PER_CTA / BT; ++tIdx) {
        const int row0 = row_base + tIdx * BT;

        // ---- X tile -> A_HI/A_LO bf16, K-contiguous, cols 40..47 zeroed ----
        for (int idx = tid; idx < BT * 10; idx += NT) {
            int r = idx / 10, q = idx - r * 10;
            float4 f = ((const float4*)(x + (size_t)(row0 + r) * IND))[q];
            *(uint32_t*)(smc + A_HI + r * APITCH + 8 * q)     = pack_bf2(f.x, f.y);
            *(uint32_t*)(smc + A_HI + r * APITCH + 8 * q + 4) = pack_bf2(f.z, f.w);
            *(uint32_t*)(smc + A_LO + r * APITCH + 8 * q)     =
                pack_bf2(f.x - bf16_of(f.x), f.y - bf16_of(f.y));
            *(uint32_t*)(smc + A_LO + r * APITCH + 8 * q + 4) =
                pack_bf2(f.z - bf16_of(f.z), f.w - bf16_of(f.w));
        }
        for (int idx = tid; idx < BT * 4; idx += NT) {
            int r = idx >> 2, q = idx & 3;
            *(uint32_t*)(smc + A_HI + r * APITCH + 80 + 4 * q) = 0u;
            *(uint32_t*)(smc + A_LO + r * APITCH + 80 + 4 * q) = 0u;
        }
        __syncthreads();

        float acc[2][8][4];
        #pragma unroll
        for (int i = 0; i < 2; ++i)
            #pragma unroll
            for (int j = 0; j < 8; ++j)
                #pragma unroll
                for (int c = 0; c < 4; ++c) acc[i][j][c] = 0.0f;

        // ---- Layer 1: K=48, 3 k-steps, 3-pass bf16 ----
        #pragma unroll
        for (int ks = 0; ks < 3; ++ks) {
            const int kk = ks * 16;
            uint32_t ah[2][4], al[2][4];
            #pragma unroll
            for (int i = 0; i < 2; ++i) {
                int abase = (warp_m * 32 + i * 16 + g) * APITCH + 2 * kk + 4 * t;
                ah[i][0] = lds_u32(smc + A_HI + abase);
                ah[i][1] = lds_u32(smc + A_HI + abase + 8 * APITCH);
                ah[i][2] = lds_u32(smc + A_HI + abase + 16);
                ah[i][3] = lds_u32(smc + A_HI + abase + 8 * APITCH + 16);
                al[i][0] = lds_u32(smc + A_LO + abase);
                al[i][1] = lds_u32(smc + A_LO + abase + 8 * APITCH);
                al[i][2] = lds_u32(smc + A_LO + abase + 16);
                al[i][3] = lds_u32(smc + A_LO + abase + 8 * APITCH + 16);
            }
            #pragma unroll
            for (int j = 0; j < 8; ++j) {
                int boff = (warp_n * 64 + j * 8 + g) * B1PITCH + 2 * kk + 4 * t;
                uint32_t bh0 = lds_u32(smc + B1_HI + boff);
                uint32_t bh1 = lds_u32(smc + B1_HI + boff + 16);
                uint32_t bl0 = lds_u32(smc + B1_LO + boff);
                uint32_t bl1 = lds_u32(smc + B1_LO + boff + 16);
                #pragma unroll
                for (int i = 0; i < 2; ++i) {
                    mma_bf16(acc[i][j], ah[i][0], ah[i][1], ah[i][2], ah[i][3], bh0, bh1);
                    mma_bf16(acc[i][j], al[i][0], al[i][1], al[i][2], al[i][3], bh0, bh1);
                    mma_bf16(acc[i][j], ah[i][0], ah[i][1], ah[i][2], ah[i][3], bl0, bl1);
                }
            }
        }
        __syncthreads();

        // ---- Epilogue 1: silu(D1 + b1) -> bf16 hi/lo h1 into A_HI/A_LO ----
        #pragma unroll
        for (int i = 0; i < 2; ++i)
            #pragma unroll
            for (int rh = 0; rh < 2; ++rh)
                #pragma unroll
                for (int j = 0; j < 8; ++j) {
                    int m = warp_m * 32 + i * 16 + g + 8 * rh;
                    int n = warp_n * 64 + j * 8 + 2 * t;
                    float v0 = silu_f(acc[i][j][rh * 2 + 0] + smf[B1F + n]);
                    float v1 = silu_f(acc[i][j][rh * 2 + 1] + smf[B1F + n + 1]);
                    *(uint32_t*)(smc + A_HI + m * APITCH + 2 * n) = pack_bf2(v0, v1);
                    *(uint32_t*)(smc + A_LO + m * APITCH + 2 * n) =
                        pack_bf2(v0 - bf16_of(v0), v1 - bf16_of(v1));
                }
        __syncthreads();

        // ---- Layer 2: K=128, 8 k-steps, 3-pass bf16 ----
        #pragma unroll
        for (int i = 0; i < 2; ++i)
            #pragma unroll
            for (int j = 0; j < 8; ++j)
                #pragma unroll
                for (int c = 0; c < 4; ++c) acc[i][j][c] = 0.0f;

        #pragma unroll
        for (int ks = 0; ks < 8; ++ks) {
            const int kk = ks * 16;
            uint32_t ah[2][4], al[2][4];
            #pragma unroll
            for (int i = 0; i < 2; ++i) {
                int abase = (warp_m * 32 + i * 16 + g) * APITCH + 2 * kk + 4 * t;
                ah[i][0] = lds_u32(smc + A_HI + abase);
                ah[i][1] = lds_u32(smc + A_HI + abase + 8 * APITCH);
                ah[i][2] = lds_u32(smc + A_HI + abase + 16);
                ah[i][3] = lds_u32(smc + A_HI + abase + 8 * APITCH + 16);
                al[i][0] = lds_u32(smc + A_LO + abase);
                al[i][1] = lds_u32(smc + A_LO + abase + 8 * APITCH);
                al[i][2] = lds_u32(smc + A_LO + abase + 16);
                al[i][3] = lds_u32(smc + A_LO + abase + 8 * APITCH + 16);
            }
            #pragma unroll
            for (int j = 0; j < 8; ++j) {
                int boff = (warp_n * 64 + j * 8 + g) * APITCH + 2 * kk + 4 * t;
                uint32_t bh0 = lds_u32(smc + B2_HI + boff);
                uint32_t bh1 = lds_u32(smc + B2_HI + boff + 16);
                uint32_t bl0 = lds_u32(smc + B2_LO + boff);
                uint32_t bl1 = lds_u32(smc + B2_LO + boff + 16);
                #pragma unroll
                for (int i = 0; i < 2; ++i) {
                    mma_bf16(acc[i][j], ah[i][0], ah[i][1], ah[i][2], ah[i][3], bh0, bh1);
                    mma_bf16(acc[i][j], al[i][0], al[i][1], al[i][2], al[i][3], bh0, bh1);
                    mma_bf16(acc[i][j], ah[i][0], ah[i][1], ah[i][2], ah[i][3], bl0, bl1);
                }
            }
        }
        __syncthreads();

        // ---- Epilogue 2: silu(D2 + b2) -> h2 fp32 (reuse A region, pitch 129 f) ----
        {
            float* h2 = (float*)smc;
            #pragma unroll
            for (int i = 0; i < 2; ++i)
                #pragma unroll
                for (int rh = 0; rh < 2; ++rh)
                    #pragma unroll
                    for (int j = 0; j < 8; ++j) {
                        int m = warp_m * 32 + i * 16 + g + 8 * rh;
                        int n = warp_n * 64 + j * 8 + 2 * t;
                        h2[m * H2PITCH + n]     = silu_f(acc[i][j][rh * 2 + 0] + smf[B2F + n]);
                        h2[m * H2PITCH + n + 1] = silu_f(acc[i][j][rh * 2 + 1] + smf[B2F + n + 1]);
                    }
        }
        __syncthreads();

        // ---- Layer 3: scalar row-dot over half the columns each ----
        {
            const float* h2 = (const float*)smc;
            int mrow = tid & 127, ch = tid >> 7;
            float s0 = 0.0f, s1 = 0.0f;
            #pragma unroll 8
            for (int c = 0; c < 64; ++c) {
                int col = ch * 64 + c;
                float v = h2[mrow * H2PITCH + col];
                s0 = fmaf(v, smf[W3F + col],       s0);
                s1 = fmaf(v, smf[W3F + 128 + col], s1);
            }
            smf[PSF + (ch * 128 + mrow) * 2 + 0] = s0;
            smf[PSF + (ch * 128 + mrow) * 2 + 1] = s1;
        }
        __syncthreads();

        if (tid < 128) {
            float mean = smf[PSF + tid * 2]     + smf[PSF + (128 + tid) * 2]     + smf[B3F + 0];
            float lv   = smf[PSF + tid * 2 + 1] + smf[PSF + (128 + tid) * 2 + 1] + smf[B3F + 1];
            lv = 5.0f   - softplus_f(5.0f - lv);
            lv = -10.0f + softplus_f(lv + 10.0f);
            int b = row0 + tid;
            out[(size_t)b * DE + de]                      = mean;
            out[(size_t)BATCH * DE + (size_t)b * DE + de] = lv;
        }
        __syncthreads();
    }
}

extern "C" void kernel_launch(void* const* d_in, const int* in_sizes, int n_in,
                              void* d_out, int out_size)
{
    const float* x  = (const float*)d_in[0];
    const float* W1 = (const float*)d_in[1];
    const float* b1 = (const float*)d_in[2];
    const float* W2 = (const float*)d_in[3];
    const float* b2 = (const float*)d_in[4];
    const float* W3 = (const float*)d_in[5];
    const float* b3 = (const float*)d_in[6];
    float* out = (float*)d_out;

    cudaFuncSetAttribute(ens_mlp_mma_kernel,
                         cudaFuncAttributeMaxDynamicSharedMemorySize, SMEM_BYTES);

    dim3 grid(DE, BSPLIT);
    ens_mlp_mma_kernel<<<grid, NT, SMEM_BYTES>>>(x, W1, b1, W2, b2, W3, b3, out);
}

// round 13
// speedup vs baseline: 3.2764x; 1.4103x over previous
#include <cuda_runtime.h>
#include <cuda_bf16.h>
#include <cstdint>

// ---------------- Problem constants ----------------
#define BATCH   4096
#define IND     40
#define HID     128
#define DE      330
#define BT      128
#define BSPLIT  4
#define ROWS_PER_CTA 1024
#define NT      256

// ---------------- SMEM byte layout (weights only) ----------------
#define B2PITCH 272                 // bytes per row, [128][136 bf16]
#define B1PITCH 112                 // bytes per row, [128][56 bf16], K padded 40->48
#define B2H_OFF 0                   // 34816
#define B2L_OFF 34816
#define B1H_OFF 69632               // 14336
#define B1L_OFF 83968
#define SCAL    98304               // float region
#define W3F 0                       // [2][128]
#define B1F 256
#define B2F 384
#define B3F 512
#define SMEM_BYTES (SCAL + 514 * 4) // 100360 B

// ---------------- helpers ----------------
__device__ __forceinline__ uint32_t smem_u32(const void* p) {
    uint32_t a;
    asm("{ .reg .u64 t; cvta.to.shared.u64 t, %1; cvt.u32.u64 %0, t; }" : "=r"(a) : "l"(p));
    return a;
}
__device__ __forceinline__ float silu_f(float v) {
    return __fdividef(v, 1.0f + __expf(-v));
}
__device__ __forceinline__ float softplus_f(float v) {
    return (v > 20.0f) ? v : log1pf(__expf(v));
}
// pack two f32 -> bf16x2 (lo = a, hi = b), single CVT
__device__ __forceinline__ uint32_t cvt_bf2(float a, float b) {
    uint32_t r;
    asm("cvt.rn.bf16x2.f32 %0, %1, %2;" : "=r"(r) : "f"(b), "f"(a));
    return r;
}
// hi/lo split of a pair: h = bf16x2(a,b); l = bf16x2(a-hi(a), b-hi(b))
__device__ __forceinline__ void split2(float a, float b, uint32_t& h, uint32_t& l) {
    h = cvt_bf2(a, b);
    float ra = __uint_as_float(h << 16);
    float rb = __uint_as_float(h & 0xffff0000u);
    l = cvt_bf2(a - ra, b - rb);
}
__device__ __forceinline__ float bf16_of(float v) {
    return __bfloat162float(__float2bfloat16_rn(v));
}

// mma.sync m16n8k16 bf16 fp32-acc (baseline PTX)
__device__ __forceinline__ void mma_bf16(float (&d)[4],
                                         uint32_t a0, uint32_t a1, uint32_t a2, uint32_t a3,
                                         uint32_t b0, uint32_t b1) {
    asm volatile(
        "mma.sync.aligned.m16n8k16.row.col.f32.bf16.bf16.f32 "
        "{%0,%1,%2,%3}, {%4,%5,%6,%7}, {%8,%9}, {%0,%1,%2,%3};"
        : "+f"(d[0]), "+f"(d[1]), "+f"(d[2]), "+f"(d[3])
        : "r"(a0), "r"(a1), "r"(a2), "r"(a3), "r"(b0), "r"(b1));
}

#define LDSM_X4(r0, r1, r2, r3, addr) \
    asm volatile("ldmatrix.sync.aligned.m8n8.x4.shared.b16 {%0,%1,%2,%3}, [%4];" \
        : "=r"(r0), "=r"(r1), "=r"(r2), "=r"(r3) : "r"(addr))

__global__ __launch_bounds__(NT, 1)
void ens_mlp_mma2_kernel(const float* __restrict__ x,
                         const float* __restrict__ W1, const float* __restrict__ b1,
                         const float* __restrict__ W2, const float* __restrict__ b2,
                         const float* __restrict__ W3, const float* __restrict__ b3,
                         float* __restrict__ out)
{
    extern __shared__ char smc[];
    float* smf = (float*)(smc + SCAL);
    const uint32_t sbase = smem_u32(smc);
    const int tid  = threadIdx.x;
    const int wid  = tid >> 5;
    const int lane = tid & 31;
    const int g = lane >> 2, t = lane & 3;
    const int de = blockIdx.x;
    const int row_base = blockIdx.y * ROWS_PER_CTA;
    const int m0 = wid * 16;           // this warp's 16-row strip

    // ---- Weight prep: bf16 hi/lo splits into SMEM ----
    {
        const float4* gW1 = (const float4*)(W1 + (size_t)de * HID * IND);
        for (int idx = tid; idx < HID * 10; idx += NT) {
            int n = idx / 10, q = idx - n * 10;
            float4 v = gW1[idx];
            char* ph = smc + B1H_OFF + n * B1PITCH + 8 * q;
            char* pl = smc + B1L_OFF + n * B1PITCH + 8 * q;
            uint32_t h0, l0, h1, l1;
            split2(v.x, v.y, h0, l0);
            split2(v.z, v.w, h1, l1);
            *(uint32_t*)(ph)     = h0;  *(uint32_t*)(ph + 4) = h1;
            *(uint32_t*)(pl)     = l0;  *(uint32_t*)(pl + 4) = l1;
        }
        // zero pad cols 40..47
        for (int idx = tid; idx < HID * 2; idx += NT) {
            int n = idx >> 1, q = idx & 1;
            *(uint32_t*)(smc + B1H_OFF + n * B1PITCH + 80 + 8 * q)     = 0u;
            *(uint32_t*)(smc + B1H_OFF + n * B1PITCH + 84 + 8 * q)     = 0u;
            *(uint32_t*)(smc + B1L_OFF + n * B1PITCH + 80 + 8 * q)     = 0u;
            *(uint32_t*)(smc + B1L_OFF + n * B1PITCH + 84 + 8 * q)     = 0u;
        }
        const float4* gW2 = (const float4*)(W2 + (size_t)de * HID * HID);
        for (int idx = tid; idx < HID * 32; idx += NT) {
            int n = idx >> 5, q = idx & 31;
            float4 v = gW2[idx];
            char* ph = smc + B2H_OFF + n * B2PITCH + 8 * q;
            char* pl = smc + B2L_OFF + n * B2PITCH + 8 * q;
            uint32_t h0, l0, h1, l1;
            split2(v.x, v.y, h0, l0);
            split2(v.z, v.w, h1, l1);
            *(uint32_t*)(ph)     = h0;  *(uint32_t*)(ph + 4) = h1;
            *(uint32_t*)(pl)     = l0;  *(uint32_t*)(pl + 4) = l1;
        }
        const float* gW3 = W3 + (size_t)de * 2 * HID;
        for (int idx = tid; idx < 256; idx += NT) smf[W3F + idx] = gW3[idx];
        for (int idx = tid; idx < HID; idx += NT) {
            smf[B1F + idx] = b1[(size_t)de * HID + idx];
            smf[B2F + idx] = b2[(size_t)de * HID + idx];
        }
        if (tid < 2) smf[B3F + tid] = b3[de * 2 + tid];
    }
    __syncthreads();   // only barrier: weights ready; tile loop is sync-free

    // per-lane ldmatrix base offsets (4 tiles: n0-7/k0-7, n0-7/k8-15, n8-15/k0-7, n8-15/k8-15)
    const uint32_t nl = ((lane >> 4) & 1) * 8 + (lane & 7);
    const uint32_t kh = (lane >> 3) & 1;
    const uint32_t b1h_base = sbase + B1H_OFF + nl * B1PITCH + kh * 16;
    const uint32_t b1l_base = sbase + B1L_OFF + nl * B1PITCH + kh * 16;
    const uint32_t b2h_base = sbase + B2H_OFF + nl * B2PITCH + kh * 16;
    const uint32_t b2l_base = sbase + B2L_OFF + nl * B2PITCH + kh * 16;

    const float b3_0 = smf[B3F + 0];
    const float b3_1 = smf[B3F + 1];

    for (int tIdx = 0; tIdx < ROWS_PER_CTA / BT; ++tIdx) {
        const int row0 = row_base + tIdx * BT;

        // ---- A1 frags straight from global x (rows m0+g, m0+8+g) ----
        uint32_t ah[3][4], al[3][4];
        {
            const float* xr0 = x + (size_t)(row0 + m0 + g) * IND;
            const float* xr1 = xr0 + 8 * IND;
            #pragma unroll
            for (int ks = 0; ks < 3; ++ks) {
                #pragma unroll
                for (int h = 0; h < 2; ++h) {
                    int col = ks * 16 + h * 8 + 2 * t;
                    if (col < IND) {
                        float2 p0 = *(const float2*)(xr0 + col);
                        float2 p1 = *(const float2*)(xr1 + col);
                        split2(p0.x, p0.y, ah[ks][2 * h + 0], al[ks][2 * h + 0]);
                        split2(p1.x, p1.y, ah[ks][2 * h + 1], al[ks][2 * h + 1]);
                    } else {
                        ah[ks][2 * h + 0] = 0u; al[ks][2 * h + 0] = 0u;
                        ah[ks][2 * h + 1] = 0u; al[ks][2 * h + 1] = 0u;
                    }
                }
            }
        }

        // ---- Layer 1: m16 x n128 x k48, 3-pass bf16 ----
        float acc1[16][4];
        #pragma unroll
        for (int j = 0; j < 16; ++j)
            #pragma unroll
            for (int c = 0; c < 4; ++c) acc1[j][c] = 0.0f;

        #pragma unroll
        for (int ks = 0; ks < 3; ++ks) {
            #pragma unroll
            for (int jp = 0; jp < 8; ++jp) {
                uint32_t bh0, bh1, bh2, bh3, bl0, bl1, bl2, bl3;
                LDSM_X4(bh0, bh1, bh2, bh3, b1h_base + jp * (16 * B1PITCH) + ks * 32);
                LDSM_X4(bl0, bl1, bl2, bl3, b1l_base + jp * (16 * B1PITCH) + ks * 32);
                mma_bf16(acc1[2*jp],   ah[ks][0], ah[ks][1], ah[ks][2], ah[ks][3], bh0, bh1);
                mma_bf16(acc1[2*jp],   al[ks][0], al[ks][1], al[ks][2], al[ks][3], bh0, bh1);
                mma_bf16(acc1[2*jp],   ah[ks][0], ah[ks][1], ah[ks][2], ah[ks][3], bl0, bl1);
                mma_bf16(acc1[2*jp+1], ah[ks][0], ah[ks][1], ah[ks][2], ah[ks][3], bh2, bh3);
                mma_bf16(acc1[2*jp+1], al[ks][0], al[ks][1], al[ks][2], al[ks][3], bh2, bh3);
                mma_bf16(acc1[2*jp+1], ah[ks][0], ah[ks][1], ah[ks][2], ah[ks][3], bl2, bl3);
            }
        }

        // ---- Epilogue 1 (registers only): silu + bf16 hi/lo split ----
        // h1h[j][0] = rows g,    packs (d0,d1);  h1h[j][1] = rows g+8, packs (d2,d3)
        uint32_t h1h[16][2], h1l[16][2];
        #pragma unroll
        for (int j = 0; j < 16; ++j) {
            float2 bb = *(const float2*)(smf + B1F + 8 * j + 2 * t);
            float v0 = silu_f(acc1[j][0] + bb.x);
            float v1 = silu_f(acc1[j][1] + bb.y);
            float v2 = silu_f(acc1[j][2] + bb.x);
            float v3 = silu_f(acc1[j][3] + bb.y);
            split2(v0, v1, h1h[j][0], h1l[j][0]);
            split2(v2, v3, h1h[j][1], h1l[j][1]);
        }

        // ---- Layer 2: m16 x n128 x k128; A-frags repacked from h1 regs ----
        float acc2[16][4];
        #pragma unroll
        for (int j = 0; j < 16; ++j)
            #pragma unroll
            for (int c = 0; c < 4; ++c) acc2[j][c] = 0.0f;

        #pragma unroll
        for (int ks = 0; ks < 8; ++ks) {
            // a0 = row g  k[16ks+2t]   = h1h[2ks][0]
            // a1 = row g8 k[16ks+2t]   = h1h[2ks][1]
            // a2 = row g  k[16ks+8+2t] = h1h[2ks+1][0]
            // a3 = row g8 k[16ks+8+2t] = h1h[2ks+1][1]
            uint32_t a0h = h1h[2*ks][0], a1h = h1h[2*ks][1];
            uint32_t a2h = h1h[2*ks+1][0], a3h = h1h[2*ks+1][1];
            uint32_t a0l = h1l[2*ks][0], a1l = h1l[2*ks][1];
            uint32_t a2l = h1l[2*ks+1][0], a3l = h1l[2*ks+1][1];
            #pragma unroll
            for (int jp = 0; jp < 8; ++jp) {
                uint32_t bh0, bh1, bh2, bh3, bl0, bl1, bl2, bl3;
                LDSM_X4(bh0, bh1, bh2, bh3, b2h_base + jp * (16 * B2PITCH) + ks * 32);
                LDSM_X4(bl0, bl1, bl2, bl3, b2l_base + jp * (16 * B2PITCH) + ks * 32);
                mma_bf16(acc2[2*jp],   a0h, a1h, a2h, a3h, bh0, bh1);
                mma_bf16(acc2[2*jp],   a0l, a1l, a2l, a3l, bh0, bh1);
                mma_bf16(acc2[2*jp],   a0h, a1h, a2h, a3h, bl0, bl1);
                mma_bf16(acc2[2*jp+1], a0h, a1h, a2h, a3h, bh2, bh3);
                mma_bf16(acc2[2*jp+1], a0l, a1l, a2l, a3l, bh2, bh3);
                mma_bf16(acc2[2*jp+1], a0h, a1h, a2h, a3h, bl2, bl3);
            }
        }

        // ---- Epilogue 2 + layer 3 (warp-local) ----
        float s0g = 0.0f, s1g = 0.0f, s0h = 0.0f, s1h = 0.0f;
        #pragma unroll
        for (int j = 0; j < 16; ++j) {
            float2 bb  = *(const float2*)(smf + B2F + 8 * j + 2 * t);
            float2 wma = *(const float2*)(smf + W3F + 8 * j + 2 * t);
            float2 wlv = *(const float2*)(smf + W3F + 128 + 8 * j + 2 * t);
            float w0 = silu_f(acc2[j][0] + bb.x);
            float w1 = silu_f(acc2[j][1] + bb.y);
            float w2 = silu_f(acc2[j][2] + bb.x);
            float w3v = silu_f(acc2[j][3] + bb.y);
            s0g = fmaf(w0, wma.x, fmaf(w1, wma.y, s0g));
            s1g = fmaf(w0, wlv.x, fmaf(w1, wlv.y, s1g));
            s0h = fmaf(w2, wma.x, fmaf(w3v, wma.y, s0h));
            s1h = fmaf(w2, wlv.x, fmaf(w3v, wlv.y, s1h));
        }
        // reduce over the 4 t-lanes (lane bits 0-1)
        #pragma unroll
        for (int off = 1; off <= 2; off <<= 1) {
            s0g += __shfl_xor_sync(0xffffffffu, s0g, off);
            s1g += __shfl_xor_sync(0xffffffffu, s1g, off);
            s0h += __shfl_xor_sync(0xffffffffu, s0h, off);
            s1h += __shfl_xor_sync(0xffffffffu, s1h, off);
        }
        if (t == 0) {
            int b0r = row0 + m0 + g;
            float mean0 = s0g + b3_0;
            float lv0   = s1g + b3_1;
            lv0 = 5.0f   - softplus_f(5.0f - lv0);
            lv0 = -10.0f + softplus_f(lv0 + 10.0f);
            out[(size_t)b0r * DE + de]                      = mean0;
            out[(size_t)BATCH * DE + (size_t)b0r * DE + de] = lv0;

            int b1r = b0r + 8;
            float mean1 = s0h + b3_0;
            float lv1   = s1h + b3_1;
            lv1 = 5.0f   - softplus_f(5.0f - lv1);
            lv1 = -10.0f + softplus_f(lv1 + 10.0f);
            out[(size_t)b1r * DE + de]                      = mean1;
            out[(size_t)BATCH * DE + (size_t)b1r * DE + de] = lv1;
        }
    }
}

extern "C" void kernel_launch(void* const* d_in, const int* in_sizes, int n_in,
                              void* d_out, int out_size)
{
    const float* x  = (const float*)d_in[0];
    const float* W1 = (const float*)d_in[1];
    const float* b1 = (const float*)d_in[2];
    const float* W2 = (const float*)d_in[3];
    const float* b2 = (const float*)d_in[4];
    const float* W3 = (const float*)d_in[5];
    const float* b3 = (const float*)d_in[6];
    float* out = (float*)d_out;

    cudaFuncSetAttribute(ens_mlp_mma2_kernel,
                         cudaFuncAttributeMaxDynamicSharedMemorySize, SMEM_BYTES);

    dim3 grid(DE, BSPLIT);
    ens_mlp_mma2_kernel<<<grid, NT, SMEM_BYTES>>>(x, W1, b1, W2, b2, W3, b3, out);
}

// round 14
// speedup vs baseline: 3.7701x; 1.1507x over previous
#include <cuda_runtime.h>
#include <cuda_bf16.h>
#include <cstdint>

// ---------------- Problem constants ----------------
#define BATCH   4096
#define IND     40
#define HID     128
#define DE      330
#define BT      128
#define BSPLIT  4
#define ROWS_PER_CTA 1024
#define NT      256

// ---------------- SMEM byte layout (weights only) ----------------
#define B2PITCH 272                 // bytes per row, [128][136 bf16]
#define B1PITCH 112                 // bytes per row, [128][56 bf16], K padded 40->48
#define B2H_OFF 0                   // 34816
#define B2L_OFF 34816
#define B1H_OFF 69632               // 14336
#define B1L_OFF 83968
#define SCAL    98304               // float region
#define W3F 0                       // [2][128]
#define B1F 256
#define B2F 384
#define B3F 512
#define SMEM_BYTES (SCAL + 514 * 4) // 100360 B -> 2 CTAs/SM

// ---------------- helpers ----------------
__device__ __forceinline__ uint32_t smem_u32(const void* p) {
    uint32_t a;
    asm("{ .reg .u64 t; cvta.to.shared.u64 t, %1; cvt.u32.u64 %0, t; }" : "=r"(a) : "l"(p));
    return a;
}
__device__ __forceinline__ float silu_f(float v) {
    return __fdividef(v, 1.0f + __expf(-v));
}
__device__ __forceinline__ float softplus_f(float v) {
    return (v > 20.0f) ? v : log1pf(__expf(v));
}
// pack two f32 -> bf16x2 (lo = a, hi = b), single CVT
__device__ __forceinline__ uint32_t cvt_bf2(float a, float b) {
    uint32_t r;
    asm("cvt.rn.bf16x2.f32 %0, %1, %2;" : "=r"(r) : "f"(b), "f"(a));
    return r;
}
// hi/lo split of a pair
__device__ __forceinline__ void split2(float a, float b, uint32_t& h, uint32_t& l) {
    h = cvt_bf2(a, b);
    float ra = __uint_as_float(h << 16);
    float rb = __uint_as_float(h & 0xffff0000u);
    l = cvt_bf2(a - ra, b - rb);
}

// mma.sync m16n8k16 bf16 fp32-acc (baseline PTX)
__device__ __forceinline__ void mma_bf16(float (&d)[4],
                                         uint32_t a0, uint32_t a1, uint32_t a2, uint32_t a3,
                                         uint32_t b0, uint32_t b1) {
    asm volatile(
        "mma.sync.aligned.m16n8k16.row.col.f32.bf16.bf16.f32 "
        "{%0,%1,%2,%3}, {%4,%5,%6,%7}, {%8,%9}, {%0,%1,%2,%3};"
        : "+f"(d[0]), "+f"(d[1]), "+f"(d[2]), "+f"(d[3])
        : "r"(a0), "r"(a1), "r"(a2), "r"(a3), "r"(b0), "r"(b1));
}

#define LDSM_X4(r0, r1, r2, r3, addr) \
    asm volatile("ldmatrix.sync.aligned.m8n8.x4.shared.b16 {%0,%1,%2,%3}, [%4];" \
        : "=r"(r0), "=r"(r1), "=r"(r2), "=r"(r3) : "r"(addr))

__global__ __launch_bounds__(NT, 2)
void ens_mlp_mma3_kernel(const float* __restrict__ x,
                         const float* __restrict__ W1, const float* __restrict__ b1,
                         const float* __restrict__ W2, const float* __restrict__ b2,
                         const float* __restrict__ W3, const float* __restrict__ b3,
                         float* __restrict__ out)
{
    extern __shared__ char smc[];
    float* smf = (float*)(smc + SCAL);
    const uint32_t sbase = smem_u32(smc);
    const int tid  = threadIdx.x;
    const int wid  = tid >> 5;
    const int lane = tid & 31;
    const int g = lane >> 2, t = lane & 3;
    const int de = blockIdx.x;
    const int row_base = blockIdx.y * ROWS_PER_CTA;
    const int m0 = wid * 16;           // this warp's 16-row strip

    // ---- Weight prep: bf16 hi/lo splits into SMEM ----
    {
        const float4* gW1 = (const float4*)(W1 + (size_t)de * HID * IND);
        for (int idx = tid; idx < HID * 10; idx += NT) {
            int n = idx / 10, q = idx - n * 10;
            float4 v = gW1[idx];
            char* ph = smc + B1H_OFF + n * B1PITCH + 8 * q;
            char* pl = smc + B1L_OFF + n * B1PITCH + 8 * q;
            uint32_t h0, l0, h1, l1;
            split2(v.x, v.y, h0, l0);
            split2(v.z, v.w, h1, l1);
            *(uint32_t*)(ph)     = h0;  *(uint32_t*)(ph + 4) = h1;
            *(uint32_t*)(pl)     = l0;  *(uint32_t*)(pl + 4) = l1;
        }
        // zero pad cols 40..47
        for (int idx = tid; idx < HID * 2; idx += NT) {
            int n = idx >> 1, q = idx & 1;
            *(uint32_t*)(smc + B1H_OFF + n * B1PITCH + 80 + 8 * q) = 0u;
            *(uint32_t*)(smc + B1H_OFF + n * B1PITCH + 84 + 8 * q) = 0u;
            *(uint32_t*)(smc + B1L_OFF + n * B1PITCH + 80 + 8 * q) = 0u;
            *(uint32_t*)(smc + B1L_OFF + n * B1PITCH + 84 + 8 * q) = 0u;
        }
        const float4* gW2 = (const float4*)(W2 + (size_t)de * HID * HID);
        for (int idx = tid; idx < HID * 32; idx += NT) {
            int n = idx >> 5, q = idx & 31;
            float4 v = gW2[idx];
            char* ph = smc + B2H_OFF + n * B2PITCH + 8 * q;
            char* pl = smc + B2L_OFF + n * B2PITCH + 8 * q;
            uint32_t h0, l0, h1, l1;
            split2(v.x, v.y, h0, l0);
            split2(v.z, v.w, h1, l1);
            *(uint32_t*)(ph)     = h0;  *(uint32_t*)(ph + 4) = h1;
            *(uint32_t*)(pl)     = l0;  *(uint32_t*)(pl + 4) = l1;
        }
        const float* gW3 = W3 + (size_t)de * 2 * HID;
        for (int idx = tid; idx < 256; idx += NT) smf[W3F + idx] = gW3[idx];
        for (int idx = tid; idx < HID; idx += NT) {
            smf[B1F + idx] = b1[(size_t)de * HID + idx];
            smf[B2F + idx] = b2[(size_t)de * HID + idx];
        }
        if (tid < 2) smf[B3F + tid] = b3[de * 2 + tid];
    }
    __syncthreads();   // only barrier; tile loop is sync-free

    // per-lane ldmatrix base (4 tiles: n0-7/k0-7, n0-7/k8-15, n8-15/k0-7, n8-15/k8-15)
    const uint32_t nl = ((lane >> 4) & 1) * 8 + (lane & 7);
    const uint32_t kh = (lane >> 3) & 1;
    const uint32_t b1h_base = sbase + B1H_OFF + nl * B1PITCH + kh * 16;
    const uint32_t b1l_base = sbase + B1L_OFF + nl * B1PITCH + kh * 16;
    const uint32_t b2h_base = sbase + B2H_OFF + nl * B2PITCH + kh * 16;
    const uint32_t b2l_base = sbase + B2L_OFF + nl * B2PITCH + kh * 16;

    const float b3_0 = smf[B3F + 0];
    const float b3_1 = smf[B3F + 1];

    for (int tIdx = 0; tIdx < ROWS_PER_CTA / BT; ++tIdx) {
        const int row0 = row_base + tIdx * BT;

        // ---- A1 frags straight from global x (rows m0+g, m0+8+g) ----
        uint32_t ah[3][4], al[3][4];
        {
            const float* xr0 = x + (size_t)(row0 + m0 + g) * IND;
            const float* xr1 = xr0 + 8 * IND;
            #pragma unroll
            for (int ks = 0; ks < 3; ++ks) {
                #pragma unroll
                for (int h = 0; h < 2; ++h) {
                    int col = ks * 16 + h * 8 + 2 * t;
                    if (col < IND) {
                        float2 p0 = *(const float2*)(xr0 + col);
                        float2 p1 = *(const float2*)(xr1 + col);
                        split2(p0.x, p0.y, ah[ks][2 * h + 0], al[ks][2 * h + 0]);
                        split2(p1.x, p1.y, ah[ks][2 * h + 1], al[ks][2 * h + 1]);
                    } else {
                        ah[ks][2 * h + 0] = 0u; al[ks][2 * h + 0] = 0u;
                        ah[ks][2 * h + 1] = 0u; al[ks][2 * h + 1] = 0u;
                    }
                }
            }
        }

        // ---- Layer 1 (jp-outer, E1 fused per group): h1 in regs ----
        uint32_t h1h[16][2], h1l[16][2];
        #pragma unroll
        for (int jp = 0; jp < 8; ++jp) {
            float acc[2][4];
            #pragma unroll
            for (int c = 0; c < 4; ++c) { acc[0][c] = 0.0f; acc[1][c] = 0.0f; }
            #pragma unroll
            for (int ks = 0; ks < 3; ++ks) {
                uint32_t bh0, bh1, bh2, bh3, bl0, bl1, bl2, bl3;
                LDSM_X4(bh0, bh1, bh2, bh3, b1h_base + jp * (16 * B1PITCH) + ks * 32);
                LDSM_X4(bl0, bl1, bl2, bl3, b1l_base + jp * (16 * B1PITCH) + ks * 32);
                mma_bf16(acc[0], ah[ks][0], ah[ks][1], ah[ks][2], ah[ks][3], bh0, bh1);
                mma_bf16(acc[0], al[ks][0], al[ks][1], al[ks][2], al[ks][3], bh0, bh1);
                mma_bf16(acc[0], ah[ks][0], ah[ks][1], ah[ks][2], ah[ks][3], bl0, bl1);
                mma_bf16(acc[1], ah[ks][0], ah[ks][1], ah[ks][2], ah[ks][3], bh2, bh3);
                mma_bf16(acc[1], al[ks][0], al[ks][1], al[ks][2], al[ks][3], bh2, bh3);
                mma_bf16(acc[1], ah[ks][0], ah[ks][1], ah[ks][2], ah[ks][3], bl2, bl3);
            }
            // E1 for j = 2jp, 2jp+1 — overlaps with next jp's HMMAs
            #pragma unroll
            for (int u = 0; u < 2; ++u) {
                int j = 2 * jp + u;
                float2 bb = *(const float2*)(smf + B1F + 8 * j + 2 * t);
                float v0 = silu_f(acc[u][0] + bb.x);
                float v1 = silu_f(acc[u][1] + bb.y);
                float v2 = silu_f(acc[u][2] + bb.x);
                float v3 = silu_f(acc[u][3] + bb.y);
                split2(v0, v1, h1h[j][0], h1l[j][0]);
                split2(v2, v3, h1h[j][1], h1l[j][1]);
            }
        }

        // ---- Layer 2 (jp-outer) + fused E2/L3 partial dots ----
        float s0g = 0.0f, s1g = 0.0f, s0h = 0.0f, s1h = 0.0f;
        #pragma unroll
        for (int jp = 0; jp < 8; ++jp) {
            float acc[2][4];
            #pragma unroll
            for (int c = 0; c < 4; ++c) { acc[0][c] = 0.0f; acc[1][c] = 0.0f; }
            #pragma unroll
            for (int ks = 0; ks < 8; ++ks) {
                uint32_t bh0, bh1, bh2, bh3, bl0, bl1, bl2, bl3;
                LDSM_X4(bh0, bh1, bh2, bh3, b2h_base + jp * (16 * B2PITCH) + ks * 32);
                LDSM_X4(bl0, bl1, bl2, bl3, b2l_base + jp * (16 * B2PITCH) + ks * 32);
                uint32_t a0h = h1h[2*ks][0],   a1h = h1h[2*ks][1];
                uint32_t a2h = h1h[2*ks+1][0], a3h = h1h[2*ks+1][1];
                uint32_t a0l = h1l[2*ks][0],   a1l = h1l[2*ks][1];
                uint32_t a2l = h1l[2*ks+1][0], a3l = h1l[2*ks+1][1];
                mma_bf16(acc[0], a0h, a1h, a2h, a3h, bh0, bh1);
                mma_bf16(acc[0], a0l, a1l, a2l, a3l, bh0, bh1);
                mma_bf16(acc[0], a0h, a1h, a2h, a3h, bl0, bl1);
                mma_bf16(acc[1], a0h, a1h, a2h, a3h, bh2, bh3);
                mma_bf16(acc[1], a0l, a1l, a2l, a3l, bh2, bh3);
                mma_bf16(acc[1], a0h, a1h, a2h, a3h, bl2, bl3);
            }
            // E2 + layer-3 partial dot for j = 2jp, 2jp+1
            #pragma unroll
            for (int u = 0; u < 2; ++u) {
                int j = 2 * jp + u;
                float2 bb  = *(const float2*)(smf + B2F + 8 * j + 2 * t);
                float2 wma = *(const float2*)(smf + W3F + 8 * j + 2 * t);
                float2 wlv = *(const float2*)(smf + W3F + 128 + 8 * j + 2 * t);
                float w0 = silu_f(acc[u][0] + bb.x);
                float w1 = silu_f(acc[u][1] + bb.y);
                float w2 = silu_f(acc[u][2] + bb.x);
                float w3v = silu_f(acc[u][3] + bb.y);
                s0g = fmaf(w0, wma.x, fmaf(w1, wma.y, s0g));
                s1g = fmaf(w0, wlv.x, fmaf(w1, wlv.y, s1g));
                s0h = fmaf(w2, wma.x, fmaf(w3v, wma.y, s0h));
                s1h = fmaf(w2, wlv.x, fmaf(w3v, wlv.y, s1h));
            }
        }

        // ---- reduce over the 4 t-lanes + store ----
        #pragma unroll
        for (int off = 1; off <= 2; off <<= 1) {
            s0g += __shfl_xor_sync(0xffffffffu, s0g, off);
            s1g += __shfl_xor_sync(0xffffffffu, s1g, off);
            s0h += __shfl_xor_sync(0xffffffffu, s0h, off);
            s1h += __shfl_xor_sync(0xffffffffu, s1h, off);
        }
        if (t == 0) {
            int b0r = row0 + m0 + g;
            float mean0 = s0g + b3_0;
            float lv0   = s1g + b3_1;
            lv0 = 5.0f   - softplus_f(5.0f - lv0);
            lv0 = -10.0f + softplus_f(lv0 + 10.0f);
            out[(size_t)b0r * DE + de]                      = mean0;
            out[(size_t)BATCH * DE + (size_t)b0r * DE + de] = lv0;

            int b1r = b0r + 8;
            float mean1 = s0h + b3_0;
            float lv1   = s1h + b3_1;
            lv1 = 5.0f   - softplus_f(5.0f - lv1);
            lv1 = -10.0f + softplus_f(lv1 + 10.0f);
            out[(size_t)b1r * DE + de]                      = mean1;
            out[(size_t)BATCH * DE + (size_t)b1r * DE + de] = lv1;
        }
    }
}

extern "C" void kernel_launch(void* const* d_in, const int* in_sizes, int n_in,
                              void* d_out, int out_size)
{
    const float* x  = (const float*)d_in[0];
    const float* W1 = (const float*)d_in[1];
    const float* b1 = (const float*)d_in[2];
    const float* W2 = (const float*)d_in[3];
    const float* b2 = (const float*)d_in[4];
    const float* W3 = (const float*)d_in[5];
    const float* b3 = (const float*)d_in[6];
    float* out = (float*)d_out;

    cudaFuncSetAttribute(ens_mlp_mma3_kernel,
                         cudaFuncAttributeMaxDynamicSharedMemorySize, SMEM_BYTES);

    dim3 grid(DE, BSPLIT);
    ens_mlp_mma3_kernel<<<grid, NT, SMEM_BYTES>>>(x, W1, b1, W2, b2, W3, b3, out);
}

// round 15
// speedup vs baseline: 3.9278x; 1.0418x over previous
#include <cuda_runtime.h>
#include <cuda_bf16.h>
#include <cstdint>

// ---------------- Problem constants ----------------
#define BATCH   4096
#define IND     40
#define HID     128
#define DE      330
#define BT      128
#define BSPLIT  8
#define ROWS_PER_CTA (BATCH / BSPLIT)   // 512
#define NT      256

// ---------------- SMEM byte layout (weights only) ----------------
#define B2PITCH 272                 // bytes per row, [128][136 bf16]
#define B1PITCH 112                 // bytes per row, [128][56 bf16], K padded 40->48
#define B2H_OFF 0                   // 34816
#define B2L_OFF 34816
#define B1H_OFF 69632               // 14336
#define B1L_OFF 83968
#define SCAL    98304               // float region
#define W3F 0                       // [2][128]
#define B1F 256
#define B2F 384
#define B3F 512
#define SMEM_BYTES (SCAL + 514 * 4) // 100360 B -> 2 CTAs/SM

// ---------------- helpers ----------------
__device__ __forceinline__ uint32_t smem_u32(const void* p) {
    uint32_t a;
    asm("{ .reg .u64 t; cvta.to.shared.u64 t, %1; cvt.u32.u64 %0, t; }" : "=r"(a) : "l"(p));
    return a;
}
// silu via single-MUFU tanh: v*sigmoid(v) = 0.5v*tanh(0.5v) + 0.5v
__device__ __forceinline__ float silu_f(float v) {
    float hv = 0.5f * v;
    float th;
    asm("tanh.approx.f32 %0, %1;" : "=f"(th) : "f"(hv));
    return fmaf(hv, th, hv);
}
__device__ __forceinline__ float softplus_f(float v) {
    return (v > 20.0f) ? v : log1pf(__expf(v));
}
// pack two f32 -> bf16x2 (lo = a, hi = b), single CVT
__device__ __forceinline__ uint32_t cvt_bf2(float a, float b) {
    uint32_t r;
    asm("cvt.rn.bf16x2.f32 %0, %1, %2;" : "=r"(r) : "f"(b), "f"(a));
    return r;
}
// hi/lo split of a pair
__device__ __forceinline__ void split2(float a, float b, uint32_t& h, uint32_t& l) {
    h = cvt_bf2(a, b);
    float ra = __uint_as_float(h << 16);
    float rb = __uint_as_float(h & 0xffff0000u);
    l = cvt_bf2(a - ra, b - rb);
}

// mma.sync m16n8k16 bf16 fp32-acc (baseline PTX)
__device__ __forceinline__ void mma_bf16(float (&d)[4],
                                         uint32_t a0, uint32_t a1, uint32_t a2, uint32_t a3,
                                         uint32_t b0, uint32_t b1) {
    asm volatile(
        "mma.sync.aligned.m16n8k16.row.col.f32.bf16.bf16.f32 "
        "{%0,%1,%2,%3}, {%4,%5,%6,%7}, {%8,%9}, {%0,%1,%2,%3};"
        : "+f"(d[0]), "+f"(d[1]), "+f"(d[2]), "+f"(d[3])
        : "r"(a0), "r"(a1), "r"(a2), "r"(a3), "r"(b0), "r"(b1));
}

#define LDSM_X4(r0, r1, r2, r3, addr) \
    asm volatile("ldmatrix.sync.aligned.m8n8.x4.shared.b16 {%0,%1,%2,%3}, [%4];" \
        : "=r"(r0), "=r"(r1), "=r"(r2), "=r"(r3) : "r"(addr))

__global__ __launch_bounds__(NT, 2)
void ens_mlp_mma4_kernel(const float* __restrict__ x,
                         const float* __restrict__ W1, const float* __restrict__ b1,
                         const float* __restrict__ W2, const float* __restrict__ b2,
                         const float* __restrict__ W3, const float* __restrict__ b3,
                         float* __restrict__ out)
{
    extern __shared__ char smc[];
    float* smf = (float*)(smc + SCAL);
    const uint32_t sbase = smem_u32(smc);
    const int tid  = threadIdx.x;
    const int wid  = tid >> 5;
    const int lane = tid & 31;
    const int g = lane >> 2, t = lane & 3;
    const int de = blockIdx.x;
    const int row_base = blockIdx.y * ROWS_PER_CTA;
    const int m0 = wid * 16;           // this warp's 16-row strip

    // ---- Weight prep: bf16 hi/lo splits into SMEM ----
    {
        const float4* gW1 = (const float4*)(W1 + (size_t)de * HID * IND);
        for (int idx = tid; idx < HID * 10; idx += NT) {
            int n = idx / 10, q = idx - n * 10;
            float4 v = gW1[idx];
            char* ph = smc + B1H_OFF + n * B1PITCH + 8 * q;
            char* pl = smc + B1L_OFF + n * B1PITCH + 8 * q;
            uint32_t h0, l0, h1, l1;
            split2(v.x, v.y, h0, l0);
            split2(v.z, v.w, h1, l1);
            *(uint32_t*)(ph)     = h0;  *(uint32_t*)(ph + 4) = h1;
            *(uint32_t*)(pl)     = l0;  *(uint32_t*)(pl + 4) = l1;
        }
        // zero pad cols 40..47
        for (int idx = tid; idx < HID * 2; idx += NT) {
            int n = idx >> 1, q = idx & 1;
            *(uint32_t*)(smc + B1H_OFF + n * B1PITCH + 80 + 8 * q) = 0u;
            *(uint32_t*)(smc + B1H_OFF + n * B1PITCH + 84 + 8 * q) = 0u;
            *(uint32_t*)(smc + B1L_OFF + n * B1PITCH + 80 + 8 * q) = 0u;
            *(uint32_t*)(smc + B1L_OFF + n * B1PITCH + 84 + 8 * q) = 0u;
        }
        const float4* gW2 = (const float4*)(W2 + (size_t)de * HID * HID);
        for (int idx = tid; idx < HID * 32; idx += NT) {
            int n = idx >> 5, q = idx & 31;
            float4 v = gW2[idx];
            char* ph = smc + B2H_OFF + n * B2PITCH + 8 * q;
            char* pl = smc + B2L_OFF + n * B2PITCH + 8 * q;
            uint32_t h0, l0, h1, l1;
            split2(v.x, v.y, h0, l0);
            split2(v.z, v.w, h1, l1);
            *(uint32_t*)(ph)     = h0;  *(uint32_t*)(ph + 4) = h1;
            *(uint32_t*)(pl)     = l0;  *(uint32_t*)(pl + 4) = l1;
        }
        const float* gW3 = W3 + (size_t)de * 2 * HID;
        for (int idx = tid; idx < 256; idx += NT) smf[W3F + idx] = gW3[idx];
        for (int idx = tid; idx < HID; idx += NT) {
            smf[B1F + idx] = b1[(size_t)de * HID + idx];
            smf[B2F + idx] = b2[(size_t)de * HID + idx];
        }
        if (tid < 2) smf[B3F + tid] = b3[de * 2 + tid];
    }
    __syncthreads();   // only barrier; tile loop is sync-free

    // per-lane ldmatrix base (4 tiles: n0-7/k0-7, n0-7/k8-15, n8-15/k0-7, n8-15/k8-15)
    const uint32_t nl = ((lane >> 4) & 1) * 8 + (lane & 7);
    const uint32_t kh = (lane >> 3) & 1;
    const uint32_t b1h_base = sbase + B1H_OFF + nl * B1PITCH + kh * 16;
    const uint32_t b1l_base = sbase + B1L_OFF + nl * B1PITCH + kh * 16;
    const uint32_t b2h_base = sbase + B2H_OFF + nl * B2PITCH + kh * 16;
    const uint32_t b2l_base = sbase + B2L_OFF + nl * B2PITCH + kh * 16;

    const float b3_0 = smf[B3F + 0];
    const float b3_1 = smf[B3F + 1];

    for (int tIdx = 0; tIdx < ROWS_PER_CTA / BT; ++tIdx) {
        const int row0 = row_base + tIdx * BT;

        // ---- A1 frags straight from global x (rows m0+g, m0+8+g) ----
        uint32_t ah[3][4], al[3][4];
        {
            const float* xr0 = x + (size_t)(row0 + m0 + g) * IND;
            const float* xr1 = xr0 + 8 * IND;
            #pragma unroll
            for (int ks = 0; ks < 3; ++ks) {
                #pragma unroll
                for (int h = 0; h < 2; ++h) {
                    int col = ks * 16 + h * 8 + 2 * t;
                    if (col < IND) {
                        float2 p0 = *(const float2*)(xr0 + col);
                        float2 p1 = *(const float2*)(xr1 + col);
                        split2(p0.x, p0.y, ah[ks][2 * h + 0], al[ks][2 * h + 0]);
                        split2(p1.x, p1.y, ah[ks][2 * h + 1], al[ks][2 * h + 1]);
                    } else {
                        ah[ks][2 * h + 0] = 0u; al[ks][2 * h + 0] = 0u;
                        ah[ks][2 * h + 1] = 0u; al[ks][2 * h + 1] = 0u;
                    }
                }
            }
        }

        // ---- Layer 1 (jp-outer, E1 fused per group): h1 in regs ----
        uint32_t h1h[16][2], h1l[16][2];
        #pragma unroll
        for (int jp = 0; jp < 8; ++jp) {
            float acc[2][4];
            #pragma unroll
            for (int c = 0; c < 4; ++c) { acc[0][c] = 0.0f; acc[1][c] = 0.0f; }
            #pragma unroll
            for (int ks = 0; ks < 3; ++ks) {
                uint32_t bh0, bh1, bh2, bh3, bl0, bl1, bl2, bl3;
                LDSM_X4(bh0, bh1, bh2, bh3, b1h_base + jp * (16 * B1PITCH) + ks * 32);
                LDSM_X4(bl0, bl1, bl2, bl3, b1l_base + jp * (16 * B1PITCH) + ks * 32);
                mma_bf16(acc[0], ah[ks][0], ah[ks][1], ah[ks][2], ah[ks][3], bh0, bh1);
                mma_bf16(acc[0], al[ks][0], al[ks][1], al[ks][2], al[ks][3], bh0, bh1);
                mma_bf16(acc[0], ah[ks][0], ah[ks][1], ah[ks][2], ah[ks][3], bl0, bl1);
                mma_bf16(acc[1], ah[ks][0], ah[ks][1], ah[ks][2], ah[ks][3], bh2, bh3);
                mma_bf16(acc[1], al[ks][0], al[ks][1], al[ks][2], al[ks][3], bh2, bh3);
                mma_bf16(acc[1], ah[ks][0], ah[ks][1], ah[ks][2], ah[ks][3], bl2, bl3);
            }
            // E1 for j = 2jp, 2jp+1 — overlaps with next jp's HMMAs
            #pragma unroll
            for (int u = 0; u < 2; ++u) {
                int j = 2 * jp + u;
                float2 bb = *(const float2*)(smf + B1F + 8 * j + 2 * t);
                float v0 = silu_f(acc[u][0] + bb.x);
                float v1 = silu_f(acc[u][1] + bb.y);
                float v2 = silu_f(acc[u][2] + bb.x);
                float v3 = silu_f(acc[u][3] + bb.y);
                split2(v0, v1, h1h[j][0], h1l[j][0]);
                split2(v2, v3, h1h[j][1], h1l[j][1]);
            }
        }

        // ---- Layer 2 (jp-outer) + fused E2/L3 partial dots ----
        float s0g = 0.0f, s1g = 0.0f, s0h = 0.0f, s1h = 0.0f;
        #pragma unroll
        for (int jp = 0; jp < 8; ++jp) {
            float acc[2][4];
            #pragma unroll
            for (int c = 0; c < 4; ++c) { acc[0][c] = 0.0f; acc[1][c] = 0.0f; }
            #pragma unroll
            for (int ks = 0; ks < 8; ++ks) {
                uint32_t bh0, bh1, bh2, bh3, bl0, bl1, bl2, bl3;
                LDSM_X4(bh0, bh1, bh2, bh3, b2h_base + jp * (16 * B2PITCH) + ks * 32);
                LDSM_X4(bl0, bl1, bl2, bl3, b2l_base + jp * (16 * B2PITCH) + ks * 32);
                uint32_t a0h = h1h[2*ks][0],   a1h = h1h[2*ks][1];
                uint32_t a2h = h1h[2*ks+1][0], a3h = h1h[2*ks+1][1];
                uint32_t a0l = h1l[2*ks][0],   a1l = h1l[2*ks][1];
                uint32_t a2l = h1l[2*ks+1][0], a3l = h1l[2*ks+1][1];
                mma_bf16(acc[0], a0h, a1h, a2h, a3h, bh0, bh1);
                mma_bf16(acc[0], a0l, a1l, a2l, a3l, bh0, bh1);
                mma_bf16(acc[0], a0h, a1h, a2h, a3h, bl0, bl1);
                mma_bf16(acc[1], a0h, a1h, a2h, a3h, bh2, bh3);
                mma_bf16(acc[1], a0l, a1l, a2l, a3l, bh2, bh3);
                mma_bf16(acc[1], a0h, a1h, a2h, a3h, bl2, bl3);
            }
            // E2 + layer-3 partial dot for j = 2jp, 2jp+1
            #pragma unroll
            for (int u = 0; u < 2; ++u) {
                int j = 2 * jp + u;
                float2 bb  = *(const float2*)(smf + B2F + 8 * j + 2 * t);
                float2 wma = *(const float2*)(smf + W3F + 8 * j + 2 * t);
                float2 wlv = *(const float2*)(smf + W3F + 128 + 8 * j + 2 * t);
                float w0 = silu_f(acc[u][0] + bb.x);
                float w1 = silu_f(acc[u][1] + bb.y);
                float w2 = silu_f(acc[u][2] + bb.x);
                float w3v = silu_f(acc[u][3] + bb.y);
                s0g = fmaf(w0, wma.x, fmaf(w1, wma.y, s0g));
                s1g = fmaf(w0, wlv.x, fmaf(w1, wlv.y, s1g));
                s0h = fmaf(w2, wma.x, fmaf(w3v, wma.y, s0h));
                s1h = fmaf(w2, wlv.x, fmaf(w3v, wlv.y, s1h));
            }
        }

        // ---- reduce over the 4 t-lanes + store ----
        #pragma unroll
        for (int off = 1; off <= 2; off <<= 1) {
            s0g += __shfl_xor_sync(0xffffffffu, s0g, off);
            s1g += __shfl_xor_sync(0xffffffffu, s1g, off);
            s0h += __shfl_xor_sync(0xffffffffu, s0h, off);
            s1h += __shfl_xor_sync(0xffffffffu, s1h, off);
        }
        if (t == 0) {
            int b0r = row0 + m0 + g;
            float mean0 = s0g + b3_0;
            float lv0   = s1g + b3_1;
            lv0 = 5.0f   - softplus_f(5.0f - lv0);
            lv0 = -10.0f + softplus_f(lv0 + 10.0f);
            out[(size_t)b0r * DE + de]                      = mean0;
            out[(size_t)BATCH * DE + (size_t)b0r * DE + de] = lv0;

            int b1r = b0r + 8;
            float mean1 = s0h + b3_0;
            float lv1   = s1h + b3_1;
            lv1 = 5.0f   - softplus_f(5.0f - lv1);
            lv1 = -10.0f + softplus_f(lv1 + 10.0f);
            out[(size_t)b1r * DE + de]                      = mean1;
            out[(size_t)BATCH * DE + (size_t)b1r * DE + de] = lv1;
        }
    }
}

extern "C" void kernel_launch(void* const* d_in, const int* in_sizes, int n_in,
                              void* d_out, int out_size)
{
    const float* x  = (const float*)d_in[0];
    const float* W1 = (const float*)d_in[1];
    const float* b1 = (const float*)d_in[2];
    const float* W2 = (const float*)d_in[3];
    const float* b2 = (const float*)d_in[4];
    const float* W3 = (const float*)d_in[5];
    const float* b3 = (const float*)d_in[6];
    float* out = (float*)d_out;

    cudaFuncSetAttribute(ens_mlp_mma4_kernel,
                         cudaFuncAttributeMaxDynamicSharedMemorySize, SMEM_BYTES);

    dim3 grid(DE, BSPLIT);
    ens_mlp_mma4_kernel<<<grid, NT, SMEM_BYTES>>>(x, W1, b1, W2, b2, W3, b3, out);
}

// round 17
// speedup vs baseline: 3.9329x; 1.0013x over previous
#include <cuda_runtime.h>
#include <cuda_bf16.h>
#include <cstdint>

// ---------------- Problem constants ----------------
#define BATCH   4096
#define IND     40
#define HID     128
#define DE      330
#define BT      128
#define BSPLIT  8
#define ROWS_PER_CTA (BATCH / BSPLIT)   // 512
#define NT      256

// ---------------- SMEM byte layout (weights only) ----------------
#define B2PITCH 272                 // bytes per row, [128][136 bf16]
#define B1PITCH 112                 // bytes per row, [128][56 bf16], K padded 40->48
#define B2H_OFF 0                   // 34816
#define B2L_OFF 34816
#define B1H_OFF 69632               // 14336
#define B1L_OFF 83968
#define SCAL    98304               // float region
#define W3F 0                       // [2][128]
#define B1F 256
#define B2F 384
#define B3F 512
#define SMEM_BYTES (SCAL + 514 * 4) // 100360 B -> 2 CTAs/SM

// ---------------- helpers ----------------
__device__ __forceinline__ uint32_t smem_u32(const void* p) {
    uint32_t a;
    asm("{ .reg .u64 t; cvta.to.shared.u64 t, %1; cvt.u32.u64 %0, t; }" : "=r"(a) : "l"(p));
    return a;
}
// silu via single-MUFU tanh: v*sigmoid(v) = 0.5v*tanh(0.5v) + 0.5v
__device__ __forceinline__ float silu_f(float v) {
    float hv = 0.5f * v;
    float th;
    asm("tanh.approx.f32 %0, %1;" : "=f"(th) : "f"(hv));
    return fmaf(hv, th, hv);
}
__device__ __forceinline__ float softplus_f(float v) {
    return (v > 20.0f) ? v : log1pf(__expf(v));
}
// pack two f32 -> bf16x2 (lo = a, hi = b), single CVT
__device__ __forceinline__ uint32_t cvt_bf2(float a, float b) {
    uint32_t r;
    asm("cvt.rn.bf16x2.f32 %0, %1, %2;" : "=r"(r) : "f"(b), "f"(a));
    return r;
}
// hi/lo split of a pair
__device__ __forceinline__ void split2(float a, float b, uint32_t& h, uint32_t& l) {
    h = cvt_bf2(a, b);
    float ra = __uint_as_float(h << 16);
    float rb = __uint_as_float(h & 0xffff0000u);
    l = cvt_bf2(a - ra, b - rb);
}

// mma.sync m16n8k16 bf16 fp32-acc (baseline PTX)
__device__ __forceinline__ void mma_bf16(float (&d)[4],
                                         uint32_t a0, uint32_t a1, uint32_t a2, uint32_t a3,
                                         uint32_t b0, uint32_t b1) {
    asm volatile(
        "mma.sync.aligned.m16n8k16.row.col.f32.bf16.bf16.f32 "
        "{%0,%1,%2,%3}, {%4,%5,%6,%7}, {%8,%9}, {%0,%1,%2,%3};"
        : "+f"(d[0]), "+f"(d[1]), "+f"(d[2]), "+f"(d[3])
        : "r"(a0), "r"(a1), "r"(a2), "r"(a3), "r"(b0), "r"(b1));
}

#define LDSM_X4(r0, r1, r2, r3, addr) \
    asm volatile("ldmatrix.sync.aligned.m8n8.x4.shared.b16 {%0,%1,%2,%3}, [%4];" \
        : "=r"(r0), "=r"(r1), "=r"(r2), "=r"(r3) : "r"(addr))

__global__ __launch_bounds__(NT, 2)
void ens_mlp_mma5_kernel(const float* __restrict__ x,
                         const float* __restrict__ W1, const float* __restrict__ b1,
                         const float* __restrict__ W2, const float* __restrict__ b2,
                         const float* __restrict__ W3, const float* __restrict__ b3,
                         float* __restrict__ out)
{
    extern __shared__ char smc[];
    float* smf = (float*)(smc + SCAL);
    const uint32_t sbase = smem_u32(smc);
    const int tid  = threadIdx.x;
    const int wid  = tid >> 5;
    const int lane = tid & 31;
    const int g = lane >> 2, t = lane & 3;
    const int de = blockIdx.x;
    const int row_base = blockIdx.y * ROWS_PER_CTA;
    const int m0 = wid * 16;           // this warp's 16-row strip

    // ---- Weight prep: bf16 hi/lo splits into SMEM ----
    {
        const float4* gW1 = (const float4*)(W1 + (size_t)de * HID * IND);
        for (int idx = tid; idx < HID * 10; idx += NT) {
            int n = idx / 10, q = idx - n * 10;
            float4 v = gW1[idx];
            char* ph = smc + B1H_OFF + n * B1PITCH + 8 * q;
            char* pl = smc + B1L_OFF + n * B1PITCH + 8 * q;
            uint32_t h0, l0, h1, l1;
            split2(v.x, v.y, h0, l0);
            split2(v.z, v.w, h1, l1);
            *(uint32_t*)(ph)     = h0;  *(uint32_t*)(ph + 4) = h1;
            *(uint32_t*)(pl)     = l0;  *(uint32_t*)(pl + 4) = l1;
        }
        // zero pad cols 40..47
        for (int idx = tid; idx < HID * 2; idx += NT) {
            int n = idx >> 1, q = idx & 1;
            *(uint32_t*)(smc + B1H_OFF + n * B1PITCH + 80 + 8 * q) = 0u;
            *(uint32_t*)(smc + B1H_OFF + n * B1PITCH + 84 + 8 * q) = 0u;
            *(uint32_t*)(smc + B1L_OFF + n * B1PITCH + 80 + 8 * q) = 0u;
            *(uint32_t*)(smc + B1L_OFF + n * B1PITCH + 84 + 8 * q) = 0u;
        }
        const float4* gW2 = (const float4*)(W2 + (size_t)de * HID * HID);
        for (int idx = tid; idx < HID * 32; idx += NT) {
            int n = idx >> 5, q = idx & 31;
            float4 v = gW2[idx];
            char* ph = smc + B2H_OFF + n * B2PITCH + 8 * q;
            char* pl = smc + B2L_OFF + n * B2PITCH + 8 * q;
            uint32_t h0, l0, h1, l1;
            split2(v.x, v.y, h0, l0);
            split2(v.z, v.w, h1, l1);
            *(uint32_t*)(ph)     = h0;  *(uint32_t*)(ph + 4) = h1;
            *(uint32_t*)(pl)     = l0;  *(uint32_t*)(pl + 4) = l1;
        }
        const float* gW3 = W3 + (size_t)de * 2 * HID;
        for (int idx = tid; idx < 256; idx += NT) smf[W3F + idx] = gW3[idx];
        for (int idx = tid; idx < HID; idx += NT) {
            smf[B1F + idx] = b1[(size_t)de * HID + idx];
            smf[B2F + idx] = b2[(size_t)de * HID + idx];
        }
        if (tid < 2) smf[B3F + tid] = b3[de * 2 + tid];
    }
    __syncthreads();   // only barrier; tile loop is sync-free

    // per-lane ldmatrix base (4 tiles: n0-7/k0-7, n0-7/k8-15, n8-15/k0-7, n8-15/k8-15)
    const uint32_t nl = ((lane >> 4) & 1) * 8 + (lane & 7);
    const uint32_t kh = (lane >> 3) & 1;
    const uint32_t b1h_base = sbase + B1H_OFF + nl * B1PITCH + kh * 16;
    const uint32_t b1l_base = sbase + B1L_OFF + nl * B1PITCH + kh * 16;
    const uint32_t b2h_base = sbase + B2H_OFF + nl * B2PITCH + kh * 16;
    const uint32_t b2l_base = sbase + B2L_OFF + nl * B2PITCH + kh * 16;

    const float b3_0 = smf[B3F + 0];
    const float b3_1 = smf[B3F + 1];

    for (int tIdx = 0; tIdx < ROWS_PER_CTA / BT; ++tIdx) {
        const int row0 = row_base + tIdx * BT;

        // ---- A1 frags straight from global x (rows m0+g, m0+8+g) ----
        uint32_t ah[3][4], al[3][4];
        {
            const float* xr0 = x + (size_t)(row0 + m0 + g) * IND;
            const float* xr1 = xr0 + 8 * IND;
            #pragma unroll
            for (int ks = 0; ks < 3; ++ks) {
                #pragma unroll
                for (int h = 0; h < 2; ++h) {
                    int col = ks * 16 + h * 8 + 2 * t;
                    if (col < IND) {
                        float2 p0 = *(const float2*)(xr0 + col);
                        float2 p1 = *(const float2*)(xr1 + col);
                        split2(p0.x, p0.y, ah[ks][2 * h + 0], al[ks][2 * h + 0]);
                        split2(p1.x, p1.y, ah[ks][2 * h + 1], al[ks][2 * h + 1]);
                    } else {
                        ah[ks][2 * h + 0] = 0u; al[ks][2 * h + 0] = 0u;
                        ah[ks][2 * h + 1] = 0u; al[ks][2 * h + 1] = 0u;
                    }
                }
            }
        }

        // ---- Layer 1: flattened (jp,ks) blocks, frag double-buffer ----
        uint32_t h1h[16][2], h1l[16][2];
        {
            uint32_t fb[2][8];
            // prologue: frags for block 0 (jp=0, ks=0)
            LDSM_X4(fb[0][0], fb[0][1], fb[0][2], fb[0][3], b1h_base);
            LDSM_X4(fb[0][4], fb[0][5], fb[0][6], fb[0][7], b1l_base);
            float acc[2][4];
            #pragma unroll
            for (int c = 0; c < 4; ++c) { acc[0][c] = 0.0f; acc[1][c] = 0.0f; }

            #pragma unroll
            for (int b = 0; b < 24; ++b) {
                const int jp = b / 3, ks = b - 3 * jp;
                // prefetch next block's frags
                if (b + 1 < 24) {
                    const int jn = (b + 1) / 3, kn = (b + 1) - 3 * jn;
                    uint32_t off = (uint32_t)(jn * (16 * B1PITCH) + kn * 32);
                    LDSM_X4(fb[(b+1)&1][0], fb[(b+1)&1][1], fb[(b+1)&1][2], fb[(b+1)&1][3],
                            b1h_base + off);
                    LDSM_X4(fb[(b+1)&1][4], fb[(b+1)&1][5], fb[(b+1)&1][6], fb[(b+1)&1][7],
                            b1l_base + off);
                }
                uint32_t* f = fb[b & 1];
                mma_bf16(acc[0], ah[ks][0], ah[ks][1], ah[ks][2], ah[ks][3], f[0], f[1]);
                mma_bf16(acc[0], al[ks][0], al[ks][1], al[ks][2], al[ks][3], f[0], f[1]);
                mma_bf16(acc[0], ah[ks][0], ah[ks][1], ah[ks][2], ah[ks][3], f[4], f[5]);
                mma_bf16(acc[1], ah[ks][0], ah[ks][1], ah[ks][2], ah[ks][3], f[2], f[3]);
                mma_bf16(acc[1], al[ks][0], al[ks][1], al[ks][2], al[ks][3], f[2], f[3]);
                mma_bf16(acc[1], ah[ks][0], ah[ks][1], ah[ks][2], ah[ks][3], f[6], f[7]);
                if (ks == 2) {
                    // E1 for j = 2jp, 2jp+1 — overlaps next jp's prefetched frags
                    #pragma unroll
                    for (int u = 0; u < 2; ++u) {
                        int j = 2 * jp + u;
                        float2 bb = *(const float2*)(smf + B1F + 8 * j + 2 * t);
                        float v0 = silu_f(acc[u][0] + bb.x);
                        float v1 = silu_f(acc[u][1] + bb.y);
                        float v2 = silu_f(acc[u][2] + bb.x);
                        float v3 = silu_f(acc[u][3] + bb.y);
                        split2(v0, v1, h1h[j][0], h1l[j][0]);
                        split2(v2, v3, h1h[j][1], h1l[j][1]);
                        acc[u][0] = 0.0f; acc[u][1] = 0.0f;
                        acc[u][2] = 0.0f; acc[u][3] = 0.0f;
                    }
                }
            }
        }

        // ---- Layer 2: flattened (jp,ks) blocks, frag double-buffer ----
        float s0g = 0.0f, s1g = 0.0f, s0h = 0.0f, s1h = 0.0f;
        {
            uint32_t fb[2][8];
            LDSM_X4(fb[0][0], fb[0][1], fb[0][2], fb[0][3], b2h_base);
            LDSM_X4(fb[0][4], fb[0][5], fb[0][6], fb[0][7], b2l_base);
            float acc[2][4];
            #pragma unroll
            for (int c = 0; c < 4; ++c) { acc[0][c] = 0.0f; acc[1][c] = 0.0f; }

            #pragma unroll
            for (int b = 0; b < 64; ++b) {
                const int jp = b >> 3, ks = b & 7;
                if (b + 1 < 64) {
                    const int jn = (b + 1) >> 3, kn = (b + 1) & 7;
                    uint32_t off = (uint32_t)(jn * (16 * B2PITCH) + kn * 32);
                    LDSM_X4(fb[(b+1)&1][0], fb[(b+1)&1][1], fb[(b+1)&1][2], fb[(b+1)&1][3],
                            b2h_base + off);
                    LDSM_X4(fb[(b+1)&1][4], fb[(b+1)&1][5], fb[(b+1)&1][6], fb[(b+1)&1][7],
                            b2l_base + off);
                }
                uint32_t* f = fb[b & 1];
                uint32_t a0h = h1h[2*ks][0],   a1h = h1h[2*ks][1];
                uint32_t a2h = h1h[2*ks+1][0], a3h = h1h[2*ks+1][1];
                uint32_t a0l = h1l[2*ks][0],   a1l = h1l[2*ks][1];
                uint32_t a2l = h1l[2*ks+1][0], a3l = h1l[2*ks+1][1];
                mma_bf16(acc[0], a0h, a1h, a2h, a3h, f[0], f[1]);
                mma_bf16(acc[0], a0l, a1l, a2l, a3l, f[0], f[1]);
                mma_bf16(acc[0], a0h, a1h, a2h, a3h, f[4], f[5]);
                mma_bf16(acc[1], a0h, a1h, a2h, a3h, f[2], f[3]);
                mma_bf16(acc[1], a0l, a1l, a2l, a3l, f[2], f[3]);
                mma_bf16(acc[1], a0h, a1h, a2h, a3h, f[6], f[7]);
                if (ks == 7) {
                    // E2 + layer-3 partial dot for j = 2jp, 2jp+1
                    #pragma unroll
                    for (int u = 0; u < 2; ++u) {
                        int j = 2 * jp + u;
                        float2 bb  = *(const float2*)(smf + B2F + 8 * j + 2 * t);
                        float2 wma = *(const float2*)(smf + W3F + 8 * j + 2 * t);
                        float2 wlv = *(const float2*)(smf + W3F + 128 + 8 * j + 2 * t);
                        float w0 = silu_f(acc[u][0] + bb.x);
                        float w1 = silu_f(acc[u][1] + bb.y);
                        float w2 = silu_f(acc[u][2] + bb.x);
                        float w3v = silu_f(acc[u][3] + bb.y);
                        s0g = fmaf(w0, wma.x, fmaf(w1, wma.y, s0g));
                        s1g = fmaf(w0, wlv.x, fmaf(w1, wlv.y, s1g));
                        s0h = fmaf(w2, wma.x, fmaf(w3v, wma.y, s0h));
                        s1h = fmaf(w2, wlv.x, fmaf(w3v, wlv.y, s1h));
                        acc[u][0] = 0.0f; acc[u][1] = 0.0f;
                        acc[u][2] = 0.0f; acc[u][3] = 0.0f;
                    }
                }
            }
        }

        // ---- reduce over the 4 t-lanes + store ----
        #pragma unroll
        for (int off = 1; off <= 2; off <<= 1) {
            s0g += __shfl_xor_sync(0xffffffffu, s0g, off);
            s1g += __shfl_xor_sync(0xffffffffu, s1g, off);
            s0h += __shfl_xor_sync(0xffffffffu, s0h, off);
            s1h += __shfl_xor_sync(0xffffffffu, s1h, off);
        }
        if (t == 0) {
            int b0r = row0 + m0 + g;
            float mean0 = s0g + b3_0;
            float lv0   = s1g + b3_1;
            lv0 = 5.0f   - softplus_f(5.0f - lv0);
            lv0 = -10.0f + softplus_f(lv0 + 10.0f);
            out[(size_t)b0r * DE + de]                      = mean0;
            out[(size_t)BATCH * DE + (size_t)b0r * DE + de] = lv0;

            int b1r = b0r + 8;
            float mean1 = s0h + b3_0;
            float lv1   = s1h + b3_1;
            lv1 = 5.0f   - softplus_f(5.0f - lv1);
            lv1 = -10.0f + softplus_f(lv1 + 10.0f);
            out[(size_t)b1r * DE + de]                      = mean1;
            out[(size_t)BATCH * DE + (size_t)b1r * DE + de] = lv1;
        }
    }
}

extern "C" void kernel_launch(void* const* d_in, const int* in_sizes, int n_in,
                              void* d_out, int out_size)
{
    const float* x  = (const float*)d_in[0];
    const float* W1 = (const float*)d_in[1];
    const float* b1 = (const float*)d_in[2];
    const float* W2 = (const float*)d_in[3];
    const float* b2 = (const float*)d_in[4];
    const float* W3 = (const float*)d_in[5];
    const float* b3 = (const float*)d_in[6];
    float* out = (float*)d_out;

    cudaFuncSetAttribute(ens_mlp_mma5_kernel,
                         cudaFuncAttributeMaxDynamicSharedMemorySize, SMEM_BYTES);

    dim3 grid(DE, BSPLIT);
    ens_mlp_mma5_kernel<<<grid, NT, SMEM_BYTES>>>(x, W1, b1, W2, b2, W3, b3, out);
}